// round 1
// baseline (speedup 1.0000x reference)
#include <cuda_runtime.h>
#include <math.h>

// ---------------- Problem constants ----------------
#define BATCH 4
#define LSEQ  1024           // LD == LE == 1024
#define DMODEL 1024
#define HEADS 16
#define DKV   64
#define DFF   4096
#define TOK   (BATCH * LSEQ) // 4096 rows
#define NBUCK 32
#define NEGINF (-1e9f)

// ---------------- Scratch (device globals; no allocation allowed) ---------
__device__ float g_xnorm[TOK * DMODEL];             // 16 MB
__device__ float g_q[TOK * DMODEL];                 // 16 MB
__device__ float g_k[TOK * DMODEL];                 // 16 MB
__device__ float g_v[TOK * DMODEL];                 // 16 MB
__device__ float g_att[TOK * DMODEL];               // 16 MB
__device__ float g_h[TOK * DMODEL];                 // 16 MB
__device__ float g_ffn[TOK * DFF];                  // 64 MB
__device__ float g_scores[(size_t)BATCH * HEADS * LSEQ * LSEQ]; // 256 MB
__device__ int   g_bucket[LSEQ];

// ---------------- RMS norm: y = x * rsqrt(mean(x^2)+eps) * w --------------
__global__ void rms_kernel(const float* __restrict__ x,
                           const float* __restrict__ w,
                           float* __restrict__ y) {
    int row = blockIdx.x;
    const float* xr = x + (size_t)row * DMODEL;
    float s = 0.f;
    for (int i = threadIdx.x; i < DMODEL; i += 256) {
        float v = xr[i];
        s += v * v;
    }
    __shared__ float red[8];
    #pragma unroll
    for (int o = 16; o; o >>= 1) s += __shfl_xor_sync(0xffffffffu, s, o);
    if ((threadIdx.x & 31) == 0) red[threadIdx.x >> 5] = s;
    __syncthreads();
    if (threadIdx.x < 8) {
        float t = red[threadIdx.x];
        #pragma unroll
        for (int o = 4; o; o >>= 1) t += __shfl_xor_sync(0xffu, t, o);
        if (threadIdx.x == 0) red[0] = rsqrtf(t * (1.0f / DMODEL) + 1e-6f);
    }
    __syncthreads();
    float inv = red[0];
    float* yr = y + (size_t)row * DMODEL;
    for (int i = threadIdx.x; i < DMODEL; i += 256)
        yr[i] = xr[i] * inv * w[i];
}

// ---------------- Generic SGEMM: C[M,N] = A[M,K] @ B[K,N] (+R)(ReLU) ------
// BM=BN=128, BK=16, 256 threads, 8x8 register tile. M,N,K multiples of tile.
template<bool RELU, bool RES>
__global__ void __launch_bounds__(256, 2)
sgemm_kernel(const float* __restrict__ A, const float* __restrict__ B,
             const float* __restrict__ R, float* __restrict__ C,
             int M, int N, int K) {
    __shared__ float As[16][128];   // [k][m]
    __shared__ float Bs[16][128];   // [k][n]
    int tid = threadIdx.x;
    int tx = tid & 15, ty = tid >> 4;
    int m0 = blockIdx.y * 128, n0 = blockIdx.x * 128;

    float acc[8][8];
    #pragma unroll
    for (int i = 0; i < 8; i++)
        #pragma unroll
        for (int j = 0; j < 8; j++) acc[i][j] = 0.f;

    for (int kt = 0; kt < K; kt += 16) {
        #pragma unroll
        for (int l = 0; l < 2; l++) {
            int f = tid + l * 256;             // 0..511 float4 slots
            // A tile: 128 rows x 16 cols -> 4 float4 per row
            int ar = f >> 2, ac = f & 3;
            float4 a = *(const float4*)(A + (size_t)(m0 + ar) * K + kt + ac * 4);
            As[ac * 4 + 0][ar] = a.x;
            As[ac * 4 + 1][ar] = a.y;
            As[ac * 4 + 2][ar] = a.z;
            As[ac * 4 + 3][ar] = a.w;
            // B tile: 16 rows x 128 cols -> 32 float4 per row
            int br = f >> 5, bc = f & 31;
            float4 b = *(const float4*)(B + (size_t)(kt + br) * N + n0 + bc * 4);
            *(float4*)&Bs[br][bc * 4] = b;
        }
        __syncthreads();
        #pragma unroll
        for (int kk = 0; kk < 16; kk++) {
            float ar[8], br[8];
            *(float4*)(ar)     = *(const float4*)&As[kk][ty * 8];
            *(float4*)(ar + 4) = *(const float4*)&As[kk][ty * 8 + 4];
            *(float4*)(br)     = *(const float4*)&Bs[kk][tx * 8];
            *(float4*)(br + 4) = *(const float4*)&Bs[kk][tx * 8 + 4];
            #pragma unroll
            for (int i = 0; i < 8; i++)
                #pragma unroll
                for (int j = 0; j < 8; j++)
                    acc[i][j] = fmaf(ar[i], br[j], acc[i][j]);
        }
        __syncthreads();
    }

    #pragma unroll
    for (int i = 0; i < 8; i++) {
        size_t roff = (size_t)(m0 + ty * 8 + i) * N + n0 + tx * 8;
        #pragma unroll
        for (int j = 0; j < 8; j += 4) {
            float4 v = make_float4(acc[i][j], acc[i][j+1], acc[i][j+2], acc[i][j+3]);
            if (RES) {
                float4 r = *(const float4*)(R + roff + j);
                v.x += r.x; v.y += r.y; v.z += r.z; v.w += r.w;
            }
            if (RELU) {
                v.x = fmaxf(v.x, 0.f); v.y = fmaxf(v.y, 0.f);
                v.z = fmaxf(v.z, 0.f); v.w = fmaxf(v.w, 0.f);
            }
            *(float4*)(C + roff + j) = v;
        }
    }
}

// ---------------- T5 relative bucket table (causal/non-bidirectional) -----
__global__ void bucket_kernel() {
    int n = threadIdx.x;   // n = q - k >= 0 clamped; 1024 threads
    int b;
    if (n < 16) {
        b = n;
    } else {
        float nf = (float)n;
        int vl = 16 + (int)(logf(nf / 16.0f) / logf(8.0f) * 16.0f);
        b = vl < (NBUCK - 1) ? vl : (NBUCK - 1);
    }
    g_bucket[n] = b;
}

// ---------------- Attention scores: S[b,h,q,k] = Q.Kt + bias --------------
// Per-block: 64x64 tile of one (b,h). K-dim = DKV = 64 (single pass).
template<bool SELF>
__global__ void __launch_bounds__(256)
scores_kernel(const float* __restrict__ Q, const float* __restrict__ KV,
              const float* __restrict__ relb, const int* __restrict__ mask,
              float* __restrict__ S) {
    __shared__ float Qs[64][65];
    __shared__ float Ks[64][65];
    int tid = threadIdx.x;
    int tx = tid & 15, ty = tid >> 4;
    int k0 = blockIdx.x * 64, q0 = blockIdx.y * 64;
    int bh = blockIdx.z;
    int b = bh >> 4, h = bh & 15;

    #pragma unroll
    for (int l = 0; l < 4; l++) {
        int f = tid + l * 256;              // 0..1023
        int row = f >> 4, cv = f & 15;      // 16 float4 per 64-float row
        float4 qv = *(const float4*)(Q + ((size_t)(b * LSEQ + q0 + row)) * DMODEL + h * DKV + cv * 4);
        Qs[row][cv*4+0]=qv.x; Qs[row][cv*4+1]=qv.y; Qs[row][cv*4+2]=qv.z; Qs[row][cv*4+3]=qv.w;
        float4 kv = *(const float4*)(KV + ((size_t)(b * LSEQ + k0 + row)) * DMODEL + h * DKV + cv * 4);
        Ks[row][cv*4+0]=kv.x; Ks[row][cv*4+1]=kv.y; Ks[row][cv*4+2]=kv.z; Ks[row][cv*4+3]=kv.w;
    }
    __syncthreads();

    float acc[4][4];
    #pragma unroll
    for (int i = 0; i < 4; i++)
        #pragma unroll
        for (int j = 0; j < 4; j++) acc[i][j] = 0.f;

    #pragma unroll 4
    for (int d = 0; d < DKV; d++) {
        float a[4], bb[4];
        #pragma unroll
        for (int i = 0; i < 4; i++) a[i] = Qs[ty * 4 + i][d];
        #pragma unroll
        for (int j = 0; j < 4; j++) bb[j] = Ks[tx * 4 + j][d];
        #pragma unroll
        for (int i = 0; i < 4; i++)
            #pragma unroll
            for (int j = 0; j < 4; j++)
                acc[i][j] = fmaf(a[i], bb[j], acc[i][j]);
    }

    #pragma unroll
    for (int i = 0; i < 4; i++) {
        int qi = q0 + ty * 4 + i;
        #pragma unroll
        for (int j = 0; j < 4; j++) {
            int ki = k0 + tx * 4 + j;
            float v = acc[i][j];
            if (SELF) {
                int delta = qi - ki;
                int bkt = g_bucket[delta > 0 ? delta : 0];
                v += relb[bkt * HEADS + h];
                bool ok = (ki <= qi) && (mask[b * LSEQ + ki] > 0);
                if (!ok) v += NEGINF;
            } else {
                if (!(mask[b * LSEQ + ki] > 0)) v += NEGINF;
            }
            S[((size_t)bh * LSEQ + qi) * LSEQ + ki] = v;
        }
    }
}

// ---------------- Row softmax over 1024 columns, in place -----------------
__global__ void softmax_kernel(float* __restrict__ S) {
    float* p = S + (size_t)blockIdx.x * LSEQ;
    int tid = threadIdx.x;
    float x0 = p[tid], x1 = p[tid + 256], x2 = p[tid + 512], x3 = p[tid + 768];
    float m = fmaxf(fmaxf(x0, x1), fmaxf(x2, x3));
    __shared__ float red[8];
    #pragma unroll
    for (int o = 16; o; o >>= 1) m = fmaxf(m, __shfl_xor_sync(0xffffffffu, m, o));
    if ((tid & 31) == 0) red[tid >> 5] = m;
    __syncthreads();
    if (tid < 8) {
        float t = red[tid];
        #pragma unroll
        for (int o = 4; o; o >>= 1) t = fmaxf(t, __shfl_xor_sync(0xffu, t, o));
        if (tid == 0) red[0] = t;
    }
    __syncthreads();
    m = red[0];
    __syncthreads();
    float e0 = __expf(x0 - m), e1 = __expf(x1 - m), e2 = __expf(x2 - m), e3 = __expf(x3 - m);
    float s = e0 + e1 + e2 + e3;
    #pragma unroll
    for (int o = 16; o; o >>= 1) s += __shfl_xor_sync(0xffffffffu, s, o);
    if ((tid & 31) == 0) red[tid >> 5] = s;
    __syncthreads();
    if (tid < 8) {
        float t = red[tid];
        #pragma unroll
        for (int o = 4; o; o >>= 1) t += __shfl_xor_sync(0xffu, t, o);
        if (tid == 0) red[0] = 1.0f / t;
    }
    __syncthreads();
    float inv = red[0];
    p[tid] = e0 * inv; p[tid + 256] = e1 * inv;
    p[tid + 512] = e2 * inv; p[tid + 768] = e3 * inv;
}

// ---------------- PV: O[b,q,h,:] = P[b,h,q,:] @ V[b,:,h,:] ----------------
// Per-block: 64 q-rows x 64 d-cols for one (b,h); K loop over 1024 keys.
__global__ void __launch_bounds__(256)
pv_kernel(const float* __restrict__ P, const float* __restrict__ V,
          float* __restrict__ O) {
    __shared__ float Ps[64][17];   // [q][k]
    __shared__ float Vs[16][65];   // [k][d]
    int tid = threadIdx.x;
    int tx = tid & 15, ty = tid >> 4;
    int q0 = blockIdx.x * 64;
    int bh = blockIdx.y;
    int b = bh >> 4, h = bh & 15;
    const float* Pb = P + (size_t)bh * LSEQ * LSEQ;

    float acc[4][4];
    #pragma unroll
    for (int i = 0; i < 4; i++)
        #pragma unroll
        for (int j = 0; j < 4; j++) acc[i][j] = 0.f;

    for (int kt = 0; kt < LSEQ; kt += 16) {
        {   // P tile 64x16 = 256 float4 (one per thread)
            int row = tid >> 2, cv = tid & 3;
            float4 pv = *(const float4*)(Pb + (size_t)(q0 + row) * LSEQ + kt + cv * 4);
            Ps[row][cv*4+0]=pv.x; Ps[row][cv*4+1]=pv.y; Ps[row][cv*4+2]=pv.z; Ps[row][cv*4+3]=pv.w;
        }
        {   // V tile 16x64 = 256 float4
            int row = tid >> 4, cv = tid & 15;
            float4 vv = *(const float4*)(V + (size_t)(b * LSEQ + kt + row) * DMODEL + h * DKV + cv * 4);
            Vs[row][cv*4+0]=vv.x; Vs[row][cv*4+1]=vv.y; Vs[row][cv*4+2]=vv.z; Vs[row][cv*4+3]=vv.w;
        }
        __syncthreads();
        #pragma unroll
        for (int kk = 0; kk < 16; kk++) {
            float a[4], bb[4];
            #pragma unroll
            for (int i = 0; i < 4; i++) a[i] = Ps[ty * 4 + i][kk];
            #pragma unroll
            for (int j = 0; j < 4; j++) bb[j] = Vs[kk][tx * 4 + j];
            #pragma unroll
            for (int i = 0; i < 4; i++)
                #pragma unroll
                for (int j = 0; j < 4; j++)
                    acc[i][j] = fmaf(a[i], bb[j], acc[i][j]);
        }
        __syncthreads();
    }
    #pragma unroll
    for (int i = 0; i < 4; i++)
        #pragma unroll
        for (int j = 0; j < 4; j++)
            O[(size_t)(b * LSEQ + q0 + ty * 4 + i) * DMODEL + h * DKV + tx * 4 + j] = acc[i][j];
}

// ---------------- Orchestration -------------------------------------------
extern "C" void kernel_launch(void* const* d_in, const int* in_sizes, int n_in,
                              void* d_out, int out_size) {
    const float* enc    = (const float*)d_in[0];
    const float* hid    = (const float*)d_in[1];
    const float* ln1_w  = (const float*)d_in[2];
    const float* sa_q   = (const float*)d_in[3];
    const float* sa_k   = (const float*)d_in[4];
    const float* sa_v   = (const float*)d_in[5];
    const float* sa_o   = (const float*)d_in[6];
    const float* relb   = (const float*)d_in[7];
    const float* ln2_w  = (const float*)d_in[8];
    const float* ca_q   = (const float*)d_in[9];
    const float* ca_k   = (const float*)d_in[10];
    const float* ca_v   = (const float*)d_in[11];
    const float* ca_o   = (const float*)d_in[12];
    const float* ln3_w  = (const float*)d_in[13];
    const float* wi     = (const float*)d_in[14];
    const float* wo     = (const float*)d_in[15];
    const float* flnw   = (const float*)d_in[16];
    const int*   emask  = (const int*)d_in[17];
    const int*   dmask  = (const int*)d_in[18];
    float* out = (float*)d_out;

    float *xn, *q, *k, *v, *att, *h, *ffn, *sc;
    cudaGetSymbolAddress((void**)&xn,  g_xnorm);
    cudaGetSymbolAddress((void**)&q,   g_q);
    cudaGetSymbolAddress((void**)&k,   g_k);
    cudaGetSymbolAddress((void**)&v,   g_v);
    cudaGetSymbolAddress((void**)&att, g_att);
    cudaGetSymbolAddress((void**)&h,   g_h);
    cudaGetSymbolAddress((void**)&ffn, g_ffn);
    cudaGetSymbolAddress((void**)&sc,  g_scores);

    dim3 gDD(DMODEL / 128, TOK / 128);      // (8, 32)   M=4096 N=1024
    dim3 gDF(DFF / 128, TOK / 128);         // (32, 32)  M=4096 N=4096
    dim3 gScore(16, 16, BATCH * HEADS);
    dim3 gPV(16, BATCH * HEADS);
    int nRows = BATCH * HEADS * LSEQ;       // 65536 softmax rows

    bucket_kernel<<<1, 1024>>>();

    // ---- Self-attention block ----
    rms_kernel<<<TOK, 256>>>(hid, ln1_w, xn);
    sgemm_kernel<false,false><<<gDD, 256>>>(xn, sa_q, nullptr, q, TOK, DMODEL, DMODEL);
    sgemm_kernel<false,false><<<gDD, 256>>>(xn, sa_k, nullptr, k, TOK, DMODEL, DMODEL);
    sgemm_kernel<false,false><<<gDD, 256>>>(xn, sa_v, nullptr, v, TOK, DMODEL, DMODEL);
    scores_kernel<true><<<gScore, 256>>>(q, k, relb, dmask, sc);
    softmax_kernel<<<nRows, 256>>>(sc);
    pv_kernel<<<gPV, 256>>>(sc, v, att);
    sgemm_kernel<false,true><<<gDD, 256>>>(att, sa_o, hid, h, TOK, DMODEL, DMODEL);

    // ---- Cross-attention block ----
    rms_kernel<<<TOK, 256>>>(h, ln2_w, xn);
    sgemm_kernel<false,false><<<gDD, 256>>>(xn,  ca_q, nullptr, q, TOK, DMODEL, DMODEL);
    sgemm_kernel<false,false><<<gDD, 256>>>(enc, ca_k, nullptr, k, TOK, DMODEL, DMODEL);
    sgemm_kernel<false,false><<<gDD, 256>>>(enc, ca_v, nullptr, v, TOK, DMODEL, DMODEL);
    scores_kernel<false><<<gScore, 256>>>(q, k, nullptr, emask, sc);
    softmax_kernel<<<nRows, 256>>>(sc);
    pv_kernel<<<gPV, 256>>>(sc, v, att);
    sgemm_kernel<false,true><<<gDD, 256>>>(att, ca_o, h, h, TOK, DMODEL, DMODEL);

    // ---- FFN block ----
    rms_kernel<<<TOK, 256>>>(h, ln3_w, xn);
    sgemm_kernel<true,false><<<gDF, 256>>>(xn, wi, nullptr, ffn, TOK, DFF, DMODEL);
    sgemm_kernel<false,true><<<gDD, 256>>>(ffn, wo, h, h, TOK, DMODEL, DFF);

    // ---- Final norm -> output ----
    rms_kernel<<<TOK, 256>>>(h, flnw, out);
}

// round 2
// speedup vs baseline: 2.3259x; 2.3259x over previous
#include <cuda_runtime.h>
#include <math.h>
#include <stdint.h>

// ---------------- Problem constants ----------------
#define BATCH 4
#define LSEQ  1024
#define DMODEL 1024
#define HEADS 16
#define DKV   64
#define DFF   4096
#define TOK   (BATCH * LSEQ)
#define NBUCK 32
#define NEGINF (-1e9f)

// ---------------- Scratch ----------------
__device__ float g_xnorm[TOK * DMODEL];
__device__ float g_q[TOK * DMODEL];
__device__ float g_k[TOK * DMODEL];
__device__ float g_v[TOK * DMODEL];
__device__ float g_att[TOK * DMODEL];
__device__ float g_h[TOK * DMODEL];
__device__ float g_ffn[TOK * DFF];
__device__ float g_scores[(size_t)BATCH * HEADS * LSEQ * LSEQ];
__device__ int   g_bucket[LSEQ];

// ---------------- helpers ----------------
__device__ __forceinline__ float f2tf32(float x) {
    uint32_t r;
    asm("cvt.rna.tf32.f32 %0, %1;" : "=r"(r) : "f"(x));
    return __uint_as_float(r);
}

__device__ __forceinline__ void mma_tf32(float (&d)[4], const uint32_t (&a)[4],
                                         const uint32_t (&b)[2]) {
    asm volatile(
        "mma.sync.aligned.m16n8k8.row.col.f32.tf32.tf32.f32 "
        "{%0,%1,%2,%3}, {%4,%5,%6,%7}, {%8,%9}, {%0,%1,%2,%3};"
        : "+f"(d[0]), "+f"(d[1]), "+f"(d[2]), "+f"(d[3])
        : "r"(a[0]), "r"(a[1]), "r"(a[2]), "r"(a[3]), "r"(b[0]), "r"(b[1]));
}

// ---------------- RMS norm ----------------
__global__ void rms_kernel(const float* __restrict__ x,
                           const float* __restrict__ w,
                           float* __restrict__ y) {
    int row = blockIdx.x;
    const float* xr = x + (size_t)row * DMODEL;
    float s = 0.f;
    for (int i = threadIdx.x; i < DMODEL; i += 256) {
        float v = xr[i];
        s += v * v;
    }
    __shared__ float red[8];
    #pragma unroll
    for (int o = 16; o; o >>= 1) s += __shfl_xor_sync(0xffffffffu, s, o);
    if ((threadIdx.x & 31) == 0) red[threadIdx.x >> 5] = s;
    __syncthreads();
    if (threadIdx.x < 8) {
        float t = red[threadIdx.x];
        #pragma unroll
        for (int o = 4; o; o >>= 1) t += __shfl_xor_sync(0xffu, t, o);
        if (threadIdx.x == 0) red[0] = rsqrtf(t * (1.0f / DMODEL) + 1e-6f);
    }
    __syncthreads();
    float inv = red[0];
    float* yr = y + (size_t)row * DMODEL;
    for (int i = threadIdx.x; i < DMODEL; i += 256)
        yr[i] = xr[i] * inv * w[i];
}

// ---------------- tf32 tensor-core GEMM: C[M,N]=A[M,K]@B[K,N] (+R)(ReLU) --
// Block 128x128, BK=32, 256 threads = 8 warps (2 M x 4 N), warp tile 64x32.
template<bool RELU, bool RES>
__global__ void __launch_bounds__(256)
mma_gemm(const float* __restrict__ A, const float* __restrict__ B,
         const float* __restrict__ R, float* __restrict__ C,
         int M, int N, int K) {
    __shared__ float As[32][132];   // [k][m], pad 4 de-conflicts tf32 frag loads
    __shared__ float Bs[32][132];   // [k][n]
    int tid = threadIdx.x;
    int warp = tid >> 5, lane = tid & 31;
    int gid = lane >> 2, tg = lane & 3;
    int wm = warp & 1, wn = warp >> 1;
    int m0 = blockIdx.y * 128, n0 = blockIdx.x * 128;

    float acc[4][4][4];
    #pragma unroll
    for (int i = 0; i < 4; i++)
        #pragma unroll
        for (int j = 0; j < 4; j++)
            #pragma unroll
            for (int l = 0; l < 4; l++) acc[i][j][l] = 0.f;

    float4 pa[4], pb[4];
    // prefetch tile 0
    #pragma unroll
    for (int i = 0; i < 4; i++) {
        int idx = tid + i * 256;
        int ar = idx >> 3, ac = (idx & 7) << 2;
        pa[i] = *(const float4*)(A + (size_t)(m0 + ar) * K + ac);
        int br = idx >> 5, bc = (idx & 31) << 2;
        pb[i] = *(const float4*)(B + (size_t)br * N + n0 + bc);
    }

    for (int kt = 0; kt < K; kt += 32) {
        // store prefetched tile into smem (tf32-rounded)
        #pragma unroll
        for (int i = 0; i < 4; i++) {
            int idx = tid + i * 256;
            int ar = idx >> 3, ac = (idx & 7) << 2;
            As[ac + 0][ar] = f2tf32(pa[i].x);
            As[ac + 1][ar] = f2tf32(pa[i].y);
            As[ac + 2][ar] = f2tf32(pa[i].z);
            As[ac + 3][ar] = f2tf32(pa[i].w);
            int br = idx >> 5, bc = (idx & 31) << 2;
            Bs[br][bc + 0] = f2tf32(pb[i].x);
            Bs[br][bc + 1] = f2tf32(pb[i].y);
            Bs[br][bc + 2] = f2tf32(pb[i].z);
            Bs[br][bc + 3] = f2tf32(pb[i].w);
        }
        __syncthreads();
        if (kt + 32 < K) {
            #pragma unroll
            for (int i = 0; i < 4; i++) {
                int idx = tid + i * 256;
                int ar = idx >> 3, ac = (idx & 7) << 2;
                pa[i] = *(const float4*)(A + (size_t)(m0 + ar) * K + kt + 32 + ac);
                int br = idx >> 5, bc = (idx & 31) << 2;
                pb[i] = *(const float4*)(B + (size_t)(kt + 32 + br) * N + n0 + bc);
            }
        }
        #pragma unroll
        for (int ks = 0; ks < 4; ks++) {
            int kk = ks * 8;
            uint32_t af[4][4], bf[4][2];
            #pragma unroll
            for (int mf = 0; mf < 4; mf++) {
                int m = wm * 64 + mf * 16 + gid;
                af[mf][0] = __float_as_uint(As[kk + tg][m]);
                af[mf][1] = __float_as_uint(As[kk + tg][m + 8]);
                af[mf][2] = __float_as_uint(As[kk + tg + 4][m]);
                af[mf][3] = __float_as_uint(As[kk + tg + 4][m + 8]);
            }
            #pragma unroll
            for (int nf = 0; nf < 4; nf++) {
                int n = wn * 32 + nf * 8 + gid;
                bf[nf][0] = __float_as_uint(Bs[kk + tg][n]);
                bf[nf][1] = __float_as_uint(Bs[kk + tg + 4][n]);
            }
            #pragma unroll
            for (int mf = 0; mf < 4; mf++)
                #pragma unroll
                for (int nf = 0; nf < 4; nf++)
                    mma_tf32(acc[mf][nf], af[mf], bf[nf]);
        }
        __syncthreads();
    }

    #pragma unroll
    for (int mf = 0; mf < 4; mf++) {
        #pragma unroll
        for (int nf = 0; nf < 4; nf++) {
            int r0 = m0 + wm * 64 + mf * 16 + gid;
            int c  = n0 + wn * 32 + nf * 8 + tg * 2;
            float2 v0 = make_float2(acc[mf][nf][0], acc[mf][nf][1]);
            float2 v1 = make_float2(acc[mf][nf][2], acc[mf][nf][3]);
            if (RES) {
                float2 a0 = *(const float2*)(R + (size_t)r0 * N + c);
                float2 a1 = *(const float2*)(R + (size_t)(r0 + 8) * N + c);
                v0.x += a0.x; v0.y += a0.y; v1.x += a1.x; v1.y += a1.y;
            }
            if (RELU) {
                v0.x = fmaxf(v0.x, 0.f); v0.y = fmaxf(v0.y, 0.f);
                v1.x = fmaxf(v1.x, 0.f); v1.y = fmaxf(v1.y, 0.f);
            }
            *(float2*)(C + (size_t)r0 * N + c) = v0;
            *(float2*)(C + (size_t)(r0 + 8) * N + c) = v1;
        }
    }
}

// ---------------- T5 relative bucket table ----------------
__global__ void bucket_kernel() {
    int n = threadIdx.x;
    int b;
    if (n < 16) {
        b = n;
    } else {
        float nf = (float)n;
        int vl = 16 + (int)(logf(nf / 16.0f) / logf(8.0f) * 16.0f);
        b = vl < (NBUCK - 1) ? vl : (NBUCK - 1);
    }
    g_bucket[n] = b;
}

// ---------------- Attention scores (tensor core) ----------------
// Per block: 128x128 tile of one (b,h). S = Q@K^T + bias. 8 warps (2Mx4N).
template<bool SELF>
__global__ void __launch_bounds__(256)
scores_kernel(const float* __restrict__ Q, const float* __restrict__ KV,
              const float* __restrict__ relb, const int* __restrict__ mask,
              float* __restrict__ S) {
    __shared__ float Qs[32][132];   // [d][q]
    __shared__ float Ks[32][132];   // [d][k]
    int tid = threadIdx.x;
    int warp = tid >> 5, lane = tid & 31;
    int gid = lane >> 2, tg = lane & 3;
    int wm = warp & 1, wn = warp >> 1;
    int k0 = blockIdx.x * 128, q0 = blockIdx.y * 128;
    int bh = blockIdx.z;
    int b = bh >> 4, h = bh & 15;

    float acc[4][4][4];
    #pragma unroll
    for (int i = 0; i < 4; i++)
        #pragma unroll
        for (int j = 0; j < 4; j++)
            #pragma unroll
            for (int l = 0; l < 4; l++) acc[i][j][l] = 0.f;

    for (int dk = 0; dk < DKV; dk += 32) {
        #pragma unroll
        for (int i = 0; i < 4; i++) {
            int idx = tid + i * 256;
            int row = idx >> 3, c = (idx & 7) << 2;
            float4 qv = *(const float4*)(Q + (size_t)(b * LSEQ + q0 + row) * DMODEL + h * DKV + dk + c);
            Qs[c + 0][row] = f2tf32(qv.x);
            Qs[c + 1][row] = f2tf32(qv.y);
            Qs[c + 2][row] = f2tf32(qv.z);
            Qs[c + 3][row] = f2tf32(qv.w);
            float4 kv = *(const float4*)(KV + (size_t)(b * LSEQ + k0 + row) * DMODEL + h * DKV + dk + c);
            Ks[c + 0][row] = f2tf32(kv.x);
            Ks[c + 1][row] = f2tf32(kv.y);
            Ks[c + 2][row] = f2tf32(kv.z);
            Ks[c + 3][row] = f2tf32(kv.w);
        }
        __syncthreads();
        #pragma unroll
        for (int ks = 0; ks < 4; ks++) {
            int kk = ks * 8;
            uint32_t af[4][4], bf[4][2];
            #pragma unroll
            for (int mf = 0; mf < 4; mf++) {
                int m = wm * 64 + mf * 16 + gid;
                af[mf][0] = __float_as_uint(Qs[kk + tg][m]);
                af[mf][1] = __float_as_uint(Qs[kk + tg][m + 8]);
                af[mf][2] = __float_as_uint(Qs[kk + tg + 4][m]);
                af[mf][3] = __float_as_uint(Qs[kk + tg + 4][m + 8]);
            }
            #pragma unroll
            for (int nf = 0; nf < 4; nf++) {
                int n = wn * 32 + nf * 8 + gid;
                bf[nf][0] = __float_as_uint(Ks[kk + tg][n]);
                bf[nf][1] = __float_as_uint(Ks[kk + tg + 4][n]);
            }
            #pragma unroll
            for (int mf = 0; mf < 4; mf++)
                #pragma unroll
                for (int nf = 0; nf < 4; nf++)
                    mma_tf32(acc[mf][nf], af[mf], bf[nf]);
        }
        __syncthreads();
    }

    #pragma unroll
    for (int mf = 0; mf < 4; mf++) {
        #pragma unroll
        for (int nf = 0; nf < 4; nf++) {
            #pragma unroll
            for (int half = 0; half < 2; half++) {
                int qi = q0 + wm * 64 + mf * 16 + gid + half * 8;
                int c  = k0 + wn * 32 + nf * 8 + tg * 2;
                float v0 = acc[mf][nf][half * 2 + 0];
                float v1 = acc[mf][nf][half * 2 + 1];
                if (SELF) {
                    int d0 = qi - c, d1 = qi - (c + 1);
                    v0 += relb[g_bucket[d0 > 0 ? d0 : 0] * HEADS + h];
                    v1 += relb[g_bucket[d1 > 0 ? d1 : 0] * HEADS + h];
                    if (!((c     <= qi) && (mask[b * LSEQ + c    ] > 0))) v0 += NEGINF;
                    if (!((c + 1 <= qi) && (mask[b * LSEQ + c + 1] > 0))) v1 += NEGINF;
                } else {
                    if (!(mask[b * LSEQ + c    ] > 0)) v0 += NEGINF;
                    if (!(mask[b * LSEQ + c + 1] > 0)) v1 += NEGINF;
                }
                *(float2*)(S + ((size_t)bh * LSEQ + qi) * LSEQ + c) = make_float2(v0, v1);
            }
        }
    }
}

// ---------------- Row softmax over 1024 columns, in place -----------------
__global__ void softmax_kernel(float* __restrict__ S) {
    float* p = S + (size_t)blockIdx.x * LSEQ;
    int tid = threadIdx.x;
    float x0 = p[tid], x1 = p[tid + 256], x2 = p[tid + 512], x3 = p[tid + 768];
    float m = fmaxf(fmaxf(x0, x1), fmaxf(x2, x3));
    __shared__ float red[8];
    #pragma unroll
    for (int o = 16; o; o >>= 1) m = fmaxf(m, __shfl_xor_sync(0xffffffffu, m, o));
    if ((tid & 31) == 0) red[tid >> 5] = m;
    __syncthreads();
    if (tid < 8) {
        float t = red[tid];
        #pragma unroll
        for (int o = 4; o; o >>= 1) t = fmaxf(t, __shfl_xor_sync(0xffu, t, o));
        if (tid == 0) red[0] = t;
    }
    __syncthreads();
    m = red[0];
    __syncthreads();
    float e0 = __expf(x0 - m), e1 = __expf(x1 - m), e2 = __expf(x2 - m), e3 = __expf(x3 - m);
    float s = e0 + e1 + e2 + e3;
    #pragma unroll
    for (int o = 16; o; o >>= 1) s += __shfl_xor_sync(0xffffffffu, s, o);
    if ((tid & 31) == 0) red[tid >> 5] = s;
    __syncthreads();
    if (tid < 8) {
        float t = red[tid];
        #pragma unroll
        for (int o = 4; o; o >>= 1) t += __shfl_xor_sync(0xffu, t, o);
        if (tid == 0) red[0] = 1.0f / t;
    }
    __syncthreads();
    float inv = red[0];
    p[tid] = e0 * inv; p[tid + 256] = e1 * inv;
    p[tid + 512] = e2 * inv; p[tid + 768] = e3 * inv;
}

// ---------------- PV (tensor core): O = P @ V ----------------
// Per block: 128 q-rows x 64 d-cols of one (b,h); K loop over 1024.
// 8 warps (4 M x 2 N), warp tile 32x32.
__global__ void __launch_bounds__(256)
pv_kernel(const float* __restrict__ P, const float* __restrict__ V,
          float* __restrict__ O) {
    __shared__ float Ps[32][132];   // [key][q]
    __shared__ float Vs[32][68];    // [key][d]
    int tid = threadIdx.x;
    int warp = tid >> 5, lane = tid & 31;
    int gid = lane >> 2, tg = lane & 3;
    int wm = warp & 3, wn = warp >> 2;
    int q0 = blockIdx.x * 128;
    int bh = blockIdx.y;
    int b = bh >> 4, h = bh & 15;
    const float* Pb = P + (size_t)bh * LSEQ * LSEQ;

    float acc[2][4][4];
    #pragma unroll
    for (int i = 0; i < 2; i++)
        #pragma unroll
        for (int j = 0; j < 4; j++)
            #pragma unroll
            for (int l = 0; l < 4; l++) acc[i][j][l] = 0.f;

    float4 pp[4], pv[2];
    #pragma unroll
    for (int i = 0; i < 4; i++) {
        int idx = tid + i * 256;
        int row = idx >> 3, c = (idx & 7) << 2;
        pp[i] = *(const float4*)(Pb + (size_t)(q0 + row) * LSEQ + c);
    }
    #pragma unroll
    for (int i = 0; i < 2; i++) {
        int idx = tid + i * 256;
        int row = idx >> 4, c = (idx & 15) << 2;
        pv[i] = *(const float4*)(V + (size_t)(b * LSEQ + row) * DMODEL + h * DKV + c);
    }

    for (int kt = 0; kt < LSEQ; kt += 32) {
        #pragma unroll
        for (int i = 0; i < 4; i++) {
            int idx = tid + i * 256;
            int row = idx >> 3, c = (idx & 7) << 2;
            Ps[c + 0][row] = f2tf32(pp[i].x);
            Ps[c + 1][row] = f2tf32(pp[i].y);
            Ps[c + 2][row] = f2tf32(pp[i].z);
            Ps[c + 3][row] = f2tf32(pp[i].w);
        }
        #pragma unroll
        for (int i = 0; i < 2; i++) {
            int idx = tid + i * 256;
            int row = idx >> 4, c = (idx & 15) << 2;
            Vs[row][c + 0] = f2tf32(pv[i].x);
            Vs[row][c + 1] = f2tf32(pv[i].y);
            Vs[row][c + 2] = f2tf32(pv[i].z);
            Vs[row][c + 3] = f2tf32(pv[i].w);
        }
        __syncthreads();
        if (kt + 32 < LSEQ) {
            #pragma unroll
            for (int i = 0; i < 4; i++) {
                int idx = tid + i * 256;
                int row = idx >> 3, c = (idx & 7) << 2;
                pp[i] = *(const float4*)(Pb + (size_t)(q0 + row) * LSEQ + kt + 32 + c);
            }
            #pragma unroll
            for (int i = 0; i < 2; i++) {
                int idx = tid + i * 256;
                int row = idx >> 4, c = (idx & 15) << 2;
                pv[i] = *(const float4*)(V + (size_t)(b * LSEQ + kt + 32 + row) * DMODEL + h * DKV + c);
            }
        }
        #pragma unroll
        for (int ks = 0; ks < 4; ks++) {
            int kk = ks * 8;
            uint32_t af[2][4], bf[4][2];
            #pragma unroll
            for (int mf = 0; mf < 2; mf++) {
                int m = wm * 32 + mf * 16 + gid;
                af[mf][0] = __float_as_uint(Ps[kk + tg][m]);
                af[mf][1] = __float_as_uint(Ps[kk + tg][m + 8]);
                af[mf][2] = __float_as_uint(Ps[kk + tg + 4][m]);
                af[mf][3] = __float_as_uint(Ps[kk + tg + 4][m + 8]);
            }
            #pragma unroll
            for (int nf = 0; nf < 4; nf++) {
                int n = wn * 32 + nf * 8 + gid;
                bf[nf][0] = __float_as_uint(Vs[kk + tg][n]);
                bf[nf][1] = __float_as_uint(Vs[kk + tg + 4][n]);
            }
            #pragma unroll
            for (int mf = 0; mf < 2; mf++)
                #pragma unroll
                for (int nf = 0; nf < 4; nf++)
                    mma_tf32(acc[mf][nf], af[mf], bf[nf]);
        }
        __syncthreads();
    }

    #pragma unroll
    for (int mf = 0; mf < 2; mf++) {
        #pragma unroll
        for (int nf = 0; nf < 4; nf++) {
            int r0 = q0 + wm * 32 + mf * 16 + gid;
            int c  = wn * 32 + nf * 8 + tg * 2;
            *(float2*)(O + (size_t)(b * LSEQ + r0) * DMODEL + h * DKV + c)
                = make_float2(acc[mf][nf][0], acc[mf][nf][1]);
            *(float2*)(O + (size_t)(b * LSEQ + r0 + 8) * DMODEL + h * DKV + c)
                = make_float2(acc[mf][nf][2], acc[mf][nf][3]);
        }
    }
}

// ---------------- Orchestration -------------------------------------------
extern "C" void kernel_launch(void* const* d_in, const int* in_sizes, int n_in,
                              void* d_out, int out_size) {
    const float* enc    = (const float*)d_in[0];
    const float* hid    = (const float*)d_in[1];
    const float* ln1_w  = (const float*)d_in[2];
    const float* sa_q   = (const float*)d_in[3];
    const float* sa_k   = (const float*)d_in[4];
    const float* sa_v   = (const float*)d_in[5];
    const float* sa_o   = (const float*)d_in[6];
    const float* relb   = (const float*)d_in[7];
    const float* ln2_w  = (const float*)d_in[8];
    const float* ca_q   = (const float*)d_in[9];
    const float* ca_k   = (const float*)d_in[10];
    const float* ca_v   = (const float*)d_in[11];
    const float* ca_o   = (const float*)d_in[12];
    const float* ln3_w  = (const float*)d_in[13];
    const float* wi     = (const float*)d_in[14];
    const float* wo     = (const float*)d_in[15];
    const float* flnw   = (const float*)d_in[16];
    const int*   emask  = (const int*)d_in[17];
    const int*   dmask  = (const int*)d_in[18];
    float* out = (float*)d_out;

    float *xn, *q, *k, *v, *att, *h, *ffn, *sc;
    cudaGetSymbolAddress((void**)&xn,  g_xnorm);
    cudaGetSymbolAddress((void**)&q,   g_q);
    cudaGetSymbolAddress((void**)&k,   g_k);
    cudaGetSymbolAddress((void**)&v,   g_v);
    cudaGetSymbolAddress((void**)&att, g_att);
    cudaGetSymbolAddress((void**)&h,   g_h);
    cudaGetSymbolAddress((void**)&ffn, g_ffn);
    cudaGetSymbolAddress((void**)&sc,  g_scores);

    dim3 gDD(DMODEL / 128, TOK / 128);
    dim3 gDF(DFF / 128, TOK / 128);
    dim3 gScore(8, 8, BATCH * HEADS);
    dim3 gPV(8, BATCH * HEADS);
    int nRows = BATCH * HEADS * LSEQ;

    bucket_kernel<<<1, 1024>>>();

    // ---- Self-attention ----
    rms_kernel<<<TOK, 256>>>(hid, ln1_w, xn);
    mma_gemm<false,false><<<gDD, 256>>>(xn, sa_q, nullptr, q, TOK, DMODEL, DMODEL);
    mma_gemm<false,false><<<gDD, 256>>>(xn, sa_k, nullptr, k, TOK, DMODEL, DMODEL);
    mma_gemm<false,false><<<gDD, 256>>>(xn, sa_v, nullptr, v, TOK, DMODEL, DMODEL);
    scores_kernel<true><<<gScore, 256>>>(q, k, relb, dmask, sc);
    softmax_kernel<<<nRows, 256>>>(sc);
    pv_kernel<<<gPV, 256>>>(sc, v, att);
    mma_gemm<false,true><<<gDD, 256>>>(att, sa_o, hid, h, TOK, DMODEL, DMODEL);

    // ---- Cross-attention ----
    rms_kernel<<<TOK, 256>>>(h, ln2_w, xn);
    mma_gemm<false,false><<<gDD, 256>>>(xn,  ca_q, nullptr, q, TOK, DMODEL, DMODEL);
    mma_gemm<false,false><<<gDD, 256>>>(enc, ca_k, nullptr, k, TOK, DMODEL, DMODEL);
    mma_gemm<false,false><<<gDD, 256>>>(enc, ca_v, nullptr, v, TOK, DMODEL, DMODEL);
    scores_kernel<false><<<gScore, 256>>>(q, k, nullptr, emask, sc);
    softmax_kernel<<<nRows, 256>>>(sc);
    pv_kernel<<<gPV, 256>>>(sc, v, att);
    mma_gemm<false,true><<<gDD, 256>>>(att, ca_o, h, h, TOK, DMODEL, DMODEL);

    // ---- FFN ----
    rms_kernel<<<TOK, 256>>>(h, ln3_w, xn);
    mma_gemm<true,false><<<gDF, 256>>>(xn, wi, nullptr, ffn, TOK, DFF, DMODEL);
    mma_gemm<false,true><<<gDD, 256>>>(ffn, wo, h, h, TOK, DMODEL, DFF);

    // ---- Final norm ----
    rms_kernel<<<TOK, 256>>>(h, flnw, out);
}

// round 3
// speedup vs baseline: 3.1441x; 1.3518x over previous
#include <cuda_runtime.h>
#include <math.h>
#include <stdint.h>

// ---------------- Problem constants ----------------
#define BATCH 4
#define LSEQ  1024
#define DMODEL 1024
#define HEADS 16
#define DKV   64
#define DFF   4096
#define TOK   (BATCH * LSEQ)
#define NBUCK 32
#define NEGINF (-1e9f)

// ---------------- Scratch ----------------
__device__ float g_xnorm[TOK * DMODEL];
__device__ float g_q[TOK * DMODEL];
__device__ float g_k[TOK * DMODEL];
__device__ float g_v[TOK * DMODEL];
__device__ float g_att[TOK * DMODEL];
__device__ float g_h[TOK * DMODEL];
__device__ float g_ffn[TOK * DFF];
__device__ float g_scores[(size_t)BATCH * HEADS * LSEQ * LSEQ];
__device__ int   g_bucket[LSEQ];

// ---------------- helpers ----------------
__device__ __forceinline__ uint32_t lds_tf32(const float* p) {
    uint32_t r;
    asm("cvt.rna.tf32.f32 %0, %1;" : "=r"(r) : "f"(*p));
    return r;
}

__device__ __forceinline__ void mma_tf32(float (&d)[4], const uint32_t (&a)[4],
                                         const uint32_t (&b)[2]) {
    asm volatile(
        "mma.sync.aligned.m16n8k8.row.col.f32.tf32.tf32.f32 "
        "{%0,%1,%2,%3}, {%4,%5,%6,%7}, {%8,%9}, {%0,%1,%2,%3};"
        : "+f"(d[0]), "+f"(d[1]), "+f"(d[2]), "+f"(d[3])
        : "r"(a[0]), "r"(a[1]), "r"(a[2]), "r"(a[3]), "r"(b[0]), "r"(b[1]));
}

__device__ __forceinline__ void cp16(float* dst, const float* src) {
    uint32_t d = (uint32_t)__cvta_generic_to_shared(dst);
    asm volatile("cp.async.cg.shared.global [%0], [%1], 16;" :: "r"(d), "l"(src));
}
__device__ __forceinline__ void cp_commit() { asm volatile("cp.async.commit_group;"); }
__device__ __forceinline__ void cp_wait0()  { asm volatile("cp.async.wait_group 0;" ::: "memory"); }

// ---------------- RMS norm ----------------
__global__ void rms_kernel(const float* __restrict__ x,
                           const float* __restrict__ w,
                           float* __restrict__ y) {
    int row = blockIdx.x;
    const float* xr = x + (size_t)row * DMODEL;
    float s = 0.f;
    for (int i = threadIdx.x; i < DMODEL; i += 256) {
        float v = xr[i];
        s += v * v;
    }
    __shared__ float red[8];
    #pragma unroll
    for (int o = 16; o; o >>= 1) s += __shfl_xor_sync(0xffffffffu, s, o);
    if ((threadIdx.x & 31) == 0) red[threadIdx.x >> 5] = s;
    __syncthreads();
    if (threadIdx.x < 8) {
        float t = red[threadIdx.x];
        #pragma unroll
        for (int o = 4; o; o >>= 1) t += __shfl_xor_sync(0xffu, t, o);
        if (threadIdx.x == 0) red[0] = rsqrtf(t * (1.0f / DMODEL) + 1e-6f);
    }
    __syncthreads();
    float inv = red[0];
    float* yr = y + (size_t)row * DMODEL;
    for (int i = threadIdx.x; i < DMODEL; i += 256)
        yr[i] = xr[i] * inv * w[i];
}

// ---------------- tf32 GEMM: C[M,N]=A@B (+R)(ReLU) ------------------------
// Block 128x128x32, 128 threads = 4 warps (2x2), warp tile 64x64.
// A smem [m][k] stride 36 (conflict-free frag loads), B smem [k][n] stride 136.
// cp.async double buffered; tf32 cvt at fragment load.
#define GA_S 36
#define GB_S 136
#define A_STG (128 * GA_S)
#define B_STG (32 * GB_S)
#define GEMM_SMEM ((2 * A_STG + 2 * B_STG) * 4)

template<bool RELU, bool RES>
__global__ void __launch_bounds__(128)
mma_gemm(const float* __restrict__ A, const float* __restrict__ B,
         const float* __restrict__ R, float* __restrict__ C,
         int M, int N, int K) {
    extern __shared__ float sm[];
    float* Asm = sm;
    float* Bsm = sm + 2 * A_STG;
    const int tid = threadIdx.x;
    const int warp = tid >> 5, lane = tid & 31;
    const int gid = lane >> 2, tg = lane & 3;
    const int wm = warp & 1, wn = warp >> 1;
    const int m0 = blockIdx.y * 128, n0 = blockIdx.x * 128;

    float acc[4][8][4];
    #pragma unroll
    for (int i = 0; i < 4; i++)
        #pragma unroll
        for (int j = 0; j < 8; j++)
            #pragma unroll
            for (int l = 0; l < 4; l++) acc[i][j][l] = 0.f;

    const float* Ag = A + (size_t)m0 * K;
    const float* Bg = B + n0;

    // A tile: 128 rows x 32 k = 1024 16B chunks; B tile: 32 k x 128 n = 1024.
    #define LOAD_TILE(kt, s) do {                                              \
        float* ad = Asm + (s) * A_STG;                                         \
        float* bd = Bsm + (s) * B_STG;                                         \
        _Pragma("unroll")                                                      \
        for (int i = 0; i < 8; i++) {                                          \
            int idx = tid + i * 128;                                           \
            int am = idx >> 3, akv = (idx & 7) << 2;                           \
            cp16(ad + am * GA_S + akv, Ag + (size_t)am * K + (kt) + akv);      \
            int bk = idx >> 5, bnv = (idx & 31) << 2;                          \
            cp16(bd + bk * GB_S + bnv, Bg + (size_t)((kt) + bk) * N + bnv);    \
        }                                                                      \
        cp_commit();                                                           \
    } while (0)

    LOAD_TILE(0, 0);
    cp_wait0();
    __syncthreads();

    int s = 0;
    for (int kt = 0; kt < K; kt += 32) {
        bool more = (kt + 32 < K);
        if (more) LOAD_TILE(kt + 32, s ^ 1);
        const float* Ab = Asm + s * A_STG;
        const float* Bb = Bsm + s * B_STG;
        #pragma unroll
        for (int ks = 0; ks < 4; ks++) {
            int kk = ks * 8;
            uint32_t af[4][4], bf[8][2];
            #pragma unroll
            for (int mf = 0; mf < 4; mf++) {
                int m = wm * 64 + mf * 16 + gid;
                af[mf][0] = lds_tf32(Ab + m * GA_S + kk + tg);
                af[mf][1] = lds_tf32(Ab + (m + 8) * GA_S + kk + tg);
                af[mf][2] = lds_tf32(Ab + m * GA_S + kk + tg + 4);
                af[mf][3] = lds_tf32(Ab + (m + 8) * GA_S + kk + tg + 4);
            }
            #pragma unroll
            for (int nf = 0; nf < 8; nf++) {
                int n = wn * 64 + nf * 8 + gid;
                bf[nf][0] = lds_tf32(Bb + (kk + tg) * GB_S + n);
                bf[nf][1] = lds_tf32(Bb + (kk + tg + 4) * GB_S + n);
            }
            #pragma unroll
            for (int mf = 0; mf < 4; mf++)
                #pragma unroll
                for (int nf = 0; nf < 8; nf++)
                    mma_tf32(acc[mf][nf], af[mf], bf[nf]);
        }
        if (more) cp_wait0();
        __syncthreads();
        s ^= 1;
    }

    #pragma unroll
    for (int mf = 0; mf < 4; mf++) {
        #pragma unroll
        for (int nf = 0; nf < 8; nf++) {
            int r0 = m0 + wm * 64 + mf * 16 + gid;
            int c  = n0 + wn * 64 + nf * 8 + tg * 2;
            float2 v0 = make_float2(acc[mf][nf][0], acc[mf][nf][1]);
            float2 v1 = make_float2(acc[mf][nf][2], acc[mf][nf][3]);
            if (RES) {
                float2 a0 = *(const float2*)(R + (size_t)r0 * N + c);
                float2 a1 = *(const float2*)(R + (size_t)(r0 + 8) * N + c);
                v0.x += a0.x; v0.y += a0.y; v1.x += a1.x; v1.y += a1.y;
            }
            if (RELU) {
                v0.x = fmaxf(v0.x, 0.f); v0.y = fmaxf(v0.y, 0.f);
                v1.x = fmaxf(v1.x, 0.f); v1.y = fmaxf(v1.y, 0.f);
            }
            *(float2*)(C + (size_t)r0 * N + c) = v0;
            *(float2*)(C + (size_t)(r0 + 8) * N + c) = v1;
        }
    }
    #undef LOAD_TILE
}

// ---------------- T5 relative bucket table ----------------
__global__ void bucket_kernel() {
    int n = threadIdx.x;
    int b;
    if (n < 16) {
        b = n;
    } else {
        float nf = (float)n;
        int vl = 16 + (int)(logf(nf / 16.0f) / logf(8.0f) * 16.0f);
        b = vl < (NBUCK - 1) ? vl : (NBUCK - 1);
    }
    g_bucket[n] = b;
}

// ---------------- Attention scores (tensor core) ----------------
// Block 128x128 tile of one (b,h), 256 threads = 8 warps (2M x 4N), warp 64x32.
// Q smem [q][d] stride 68, K smem [k][d] stride 68; single K pass (DKV=64).
#define SC_S 68
#define SC_SMEM ((128 * SC_S * 2) * 4)

template<bool SELF>
__global__ void __launch_bounds__(256)
scores_kernel(const float* __restrict__ Q, const float* __restrict__ KV,
              const float* __restrict__ relb, const int* __restrict__ mask,
              float* __restrict__ S) {
    extern __shared__ float sm[];
    float* Qs = sm;
    float* Ks = sm + 128 * SC_S;
    int tid = threadIdx.x;
    int warp = tid >> 5, lane = tid & 31;
    int gid = lane >> 2, tg = lane & 3;
    int wm = warp & 1, wn = warp >> 1;
    int k0 = blockIdx.x * 128, q0 = blockIdx.y * 128;
    int bh = blockIdx.z;
    int b = bh >> 4, h = bh & 15;

    // fill: 128 rows x 16 chunks each for Q and K
    #pragma unroll
    for (int i = 0; i < 8; i++) {
        int idx = tid + i * 256;
        int row = idx >> 4, cv = (idx & 15) << 2;
        cp16(Qs + row * SC_S + cv,
             Q + (size_t)(b * LSEQ + q0 + row) * DMODEL + h * DKV + cv);
        cp16(Ks + row * SC_S + cv,
             KV + (size_t)(b * LSEQ + k0 + row) * DMODEL + h * DKV + cv);
    }
    cp_commit();
    cp_wait0();
    __syncthreads();

    float acc[4][4][4];
    #pragma unroll
    for (int i = 0; i < 4; i++)
        #pragma unroll
        for (int j = 0; j < 4; j++)
            #pragma unroll
            for (int l = 0; l < 4; l++) acc[i][j][l] = 0.f;

    #pragma unroll
    for (int ks = 0; ks < 8; ks++) {
        int kk = ks * 8;
        uint32_t af[4][4], bf[4][2];
        #pragma unroll
        for (int mf = 0; mf < 4; mf++) {
            int m = wm * 64 + mf * 16 + gid;
            af[mf][0] = lds_tf32(Qs + m * SC_S + kk + tg);
            af[mf][1] = lds_tf32(Qs + (m + 8) * SC_S + kk + tg);
            af[mf][2] = lds_tf32(Qs + m * SC_S + kk + tg + 4);
            af[mf][3] = lds_tf32(Qs + (m + 8) * SC_S + kk + tg + 4);
        }
        #pragma unroll
        for (int nf = 0; nf < 4; nf++) {
            int n = wn * 32 + nf * 8 + gid;
            bf[nf][0] = lds_tf32(Ks + n * SC_S + kk + tg);
            bf[nf][1] = lds_tf32(Ks + n * SC_S + kk + tg + 4);
        }
        #pragma unroll
        for (int mf = 0; mf < 4; mf++)
            #pragma unroll
            for (int nf = 0; nf < 4; nf++)
                mma_tf32(acc[mf][nf], af[mf], bf[nf]);
    }

    #pragma unroll
    for (int mf = 0; mf < 4; mf++) {
        #pragma unroll
        for (int nf = 0; nf < 4; nf++) {
            #pragma unroll
            for (int half = 0; half < 2; half++) {
                int qi = q0 + wm * 64 + mf * 16 + gid + half * 8;
                int c  = k0 + wn * 32 + nf * 8 + tg * 2;
                float v0 = acc[mf][nf][half * 2 + 0];
                float v1 = acc[mf][nf][half * 2 + 1];
                if (SELF) {
                    int d0 = qi - c, d1 = qi - (c + 1);
                    v0 += relb[g_bucket[d0 > 0 ? d0 : 0] * HEADS + h];
                    v1 += relb[g_bucket[d1 > 0 ? d1 : 0] * HEADS + h];
                    if (!((c     <= qi) && (mask[b * LSEQ + c    ] > 0))) v0 += NEGINF;
                    if (!((c + 1 <= qi) && (mask[b * LSEQ + c + 1] > 0))) v1 += NEGINF;
                } else {
                    if (!(mask[b * LSEQ + c    ] > 0)) v0 += NEGINF;
                    if (!(mask[b * LSEQ + c + 1] > 0)) v1 += NEGINF;
                }
                *(float2*)(S + ((size_t)bh * LSEQ + qi) * LSEQ + c) = make_float2(v0, v1);
            }
        }
    }
}

// ---------------- Row softmax over 1024 columns, in place -----------------
__global__ void softmax_kernel(float* __restrict__ S) {
    float* p = S + (size_t)blockIdx.x * LSEQ;
    int tid = threadIdx.x;
    float x0 = p[tid], x1 = p[tid + 256], x2 = p[tid + 512], x3 = p[tid + 768];
    float m = fmaxf(fmaxf(x0, x1), fmaxf(x2, x3));
    __shared__ float red[8];
    #pragma unroll
    for (int o = 16; o; o >>= 1) m = fmaxf(m, __shfl_xor_sync(0xffffffffu, m, o));
    if ((tid & 31) == 0) red[tid >> 5] = m;
    __syncthreads();
    if (tid < 8) {
        float t = red[tid];
        #pragma unroll
        for (int o = 4; o; o >>= 1) t = fmaxf(t, __shfl_xor_sync(0xffu, t, o));
        if (tid == 0) red[0] = t;
    }
    __syncthreads();
    m = red[0];
    __syncthreads();
    float e0 = __expf(x0 - m), e1 = __expf(x1 - m), e2 = __expf(x2 - m), e3 = __expf(x3 - m);
    float s = e0 + e1 + e2 + e3;
    #pragma unroll
    for (int o = 16; o; o >>= 1) s += __shfl_xor_sync(0xffffffffu, s, o);
    if ((tid & 31) == 0) red[tid >> 5] = s;
    __syncthreads();
    if (tid < 8) {
        float t = red[tid];
        #pragma unroll
        for (int o = 4; o; o >>= 1) t += __shfl_xor_sync(0xffu, t, o);
        if (tid == 0) red[0] = 1.0f / t;
    }
    __syncthreads();
    float inv = red[0];
    p[tid] = e0 * inv; p[tid + 256] = e1 * inv;
    p[tid + 512] = e2 * inv; p[tid + 768] = e3 * inv;
}

// ---------------- PV (tensor core): O = P @ V ----------------
// Block 128 q x 64 d of one (b,h); 256 threads = 8 warps (4M x 2N), warp 32x32.
// P smem [q][k] stride 36; V smem [k][d] stride 72; cp.async double buffered.
#define PV_PS 36
#define PV_VS 72
#define P_STG (128 * PV_PS)
#define V_STG (32 * PV_VS)
#define PV_SMEM ((2 * P_STG + 2 * V_STG) * 4)

__global__ void __launch_bounds__(256)
pv_kernel(const float* __restrict__ P, const float* __restrict__ V,
          float* __restrict__ O) {
    extern __shared__ float sm[];
    float* Psm = sm;
    float* Vsm = sm + 2 * P_STG;
    int tid = threadIdx.x;
    int warp = tid >> 5, lane = tid & 31;
    int gid = lane >> 2, tg = lane & 3;
    int wm = warp & 3, wn = warp >> 2;
    int q0 = blockIdx.x * 128;
    int bh = blockIdx.y;
    int b = bh >> 4, h = bh & 15;
    const float* Pb = P + ((size_t)bh * LSEQ + q0) * LSEQ;
    const float* Vb = V + (size_t)(b * LSEQ) * DMODEL + h * DKV;

    float acc[2][4][4];
    #pragma unroll
    for (int i = 0; i < 2; i++)
        #pragma unroll
        for (int j = 0; j < 4; j++)
            #pragma unroll
            for (int l = 0; l < 4; l++) acc[i][j][l] = 0.f;

    #define PV_LOAD(kt, s) do {                                               \
        float* pd = Psm + (s) * P_STG;                                        \
        float* vd = Vsm + (s) * V_STG;                                        \
        _Pragma("unroll")                                                     \
        for (int i = 0; i < 4; i++) {                                         \
            int idx = tid + i * 256;                                          \
            int row = idx >> 3, cv = (idx & 7) << 2;                          \
            cp16(pd + row * PV_PS + cv, Pb + (size_t)row * LSEQ + (kt) + cv); \
        }                                                                     \
        _Pragma("unroll")                                                     \
        for (int i = 0; i < 2; i++) {                                         \
            int idx = tid + i * 256;                                          \
            int kr = idx >> 4, dv = (idx & 15) << 2;                          \
            cp16(vd + kr * PV_VS + dv, Vb + (size_t)((kt) + kr) * DMODEL + dv); \
        }                                                                     \
        cp_commit();                                                          \
    } while (0)

    PV_LOAD(0, 0);
    cp_wait0();
    __syncthreads();

    int s = 0;
    for (int kt = 0; kt < LSEQ; kt += 32) {
        bool more = (kt + 32 < LSEQ);
        if (more) PV_LOAD(kt + 32, s ^ 1);
        const float* Pp = Psm + s * P_STG;
        const float* Vp = Vsm + s * V_STG;
        #pragma unroll
        for (int ks = 0; ks < 4; ks++) {
            int kk = ks * 8;
            uint32_t af[2][4], bf[4][2];
            #pragma unroll
            for (int mf = 0; mf < 2; mf++) {
                int m = wm * 32 + mf * 16 + gid;
                af[mf][0] = lds_tf32(Pp + m * PV_PS + kk + tg);
                af[mf][1] = lds_tf32(Pp + (m + 8) * PV_PS + kk + tg);
                af[mf][2] = lds_tf32(Pp + m * PV_PS + kk + tg + 4);
                af[mf][3] = lds_tf32(Pp + (m + 8) * PV_PS + kk + tg + 4);
            }
            #pragma unroll
            for (int nf = 0; nf < 4; nf++) {
                int n = wn * 32 + nf * 8 + gid;
                bf[nf][0] = lds_tf32(Vp + (kk + tg) * PV_VS + n);
                bf[nf][1] = lds_tf32(Vp + (kk + tg + 4) * PV_VS + n);
            }
            #pragma unroll
            for (int mf = 0; mf < 2; mf++)
                #pragma unroll
                for (int nf = 0; nf < 4; nf++)
                    mma_tf32(acc[mf][nf], af[mf], bf[nf]);
        }
        if (more) cp_wait0();
        __syncthreads();
        s ^= 1;
    }

    #pragma unroll
    for (int mf = 0; mf < 2; mf++) {
        #pragma unroll
        for (int nf = 0; nf < 4; nf++) {
            int r0 = q0 + wm * 32 + mf * 16 + gid;
            int c  = wn * 32 + nf * 8 + tg * 2;
            *(float2*)(O + (size_t)(b * LSEQ + r0) * DMODEL + h * DKV + c)
                = make_float2(acc[mf][nf][0], acc[mf][nf][1]);
            *(float2*)(O + (size_t)(b * LSEQ + r0 + 8) * DMODEL + h * DKV + c)
                = make_float2(acc[mf][nf][2], acc[mf][nf][3]);
        }
    }
    #undef PV_LOAD
}

// ---------------- Orchestration -------------------------------------------
extern "C" void kernel_launch(void* const* d_in, const int* in_sizes, int n_in,
                              void* d_out, int out_size) {
    const float* enc    = (const float*)d_in[0];
    const float* hid    = (const float*)d_in[1];
    const float* ln1_w  = (const float*)d_in[2];
    const float* sa_q   = (const float*)d_in[3];
    const float* sa_k   = (const float*)d_in[4];
    const float* sa_v   = (const float*)d_in[5];
    const float* sa_o   = (const float*)d_in[6];
    const float* relb   = (const float*)d_in[7];
    const float* ln2_w  = (const float*)d_in[8];
    const float* ca_q   = (const float*)d_in[9];
    const float* ca_k   = (const float*)d_in[10];
    const float* ca_v   = (const float*)d_in[11];
    const float* ca_o   = (const float*)d_in[12];
    const float* ln3_w  = (const float*)d_in[13];
    const float* wi     = (const float*)d_in[14];
    const float* wo     = (const float*)d_in[15];
    const float* flnw   = (const float*)d_in[16];
    const int*   emask  = (const int*)d_in[17];
    const int*   dmask  = (const int*)d_in[18];
    float* out = (float*)d_out;

    float *xn, *q, *k, *v, *att, *h, *ffn, *sc;
    cudaGetSymbolAddress((void**)&xn,  g_xnorm);
    cudaGetSymbolAddress((void**)&q,   g_q);
    cudaGetSymbolAddress((void**)&k,   g_k);
    cudaGetSymbolAddress((void**)&v,   g_v);
    cudaGetSymbolAddress((void**)&att, g_att);
    cudaGetSymbolAddress((void**)&h,   g_h);
    cudaGetSymbolAddress((void**)&ffn, g_ffn);
    cudaGetSymbolAddress((void**)&sc,  g_scores);

    cudaFuncSetAttribute(mma_gemm<false,false>, cudaFuncAttributeMaxDynamicSharedMemorySize, GEMM_SMEM);
    cudaFuncSetAttribute(mma_gemm<false,true>,  cudaFuncAttributeMaxDynamicSharedMemorySize, GEMM_SMEM);
    cudaFuncSetAttribute(mma_gemm<true,false>,  cudaFuncAttributeMaxDynamicSharedMemorySize, GEMM_SMEM);
    cudaFuncSetAttribute(scores_kernel<true>,   cudaFuncAttributeMaxDynamicSharedMemorySize, SC_SMEM);
    cudaFuncSetAttribute(scores_kernel<false>,  cudaFuncAttributeMaxDynamicSharedMemorySize, SC_SMEM);
    cudaFuncSetAttribute(pv_kernel,             cudaFuncAttributeMaxDynamicSharedMemorySize, PV_SMEM);

    dim3 gDD(DMODEL / 128, TOK / 128);
    dim3 gDF(DFF / 128, TOK / 128);
    dim3 gScore(8, 8, BATCH * HEADS);
    dim3 gPV(8, BATCH * HEADS);
    int nRows = BATCH * HEADS * LSEQ;

    bucket_kernel<<<1, 1024>>>();

    // ---- Self-attention ----
    rms_kernel<<<TOK, 256>>>(hid, ln1_w, xn);
    mma_gemm<false,false><<<gDD, 128, GEMM_SMEM>>>(xn, sa_q, nullptr, q, TOK, DMODEL, DMODEL);
    mma_gemm<false,false><<<gDD, 128, GEMM_SMEM>>>(xn, sa_k, nullptr, k, TOK, DMODEL, DMODEL);
    mma_gemm<false,false><<<gDD, 128, GEMM_SMEM>>>(xn, sa_v, nullptr, v, TOK, DMODEL, DMODEL);
    scores_kernel<true><<<gScore, 256, SC_SMEM>>>(q, k, relb, dmask, sc);
    softmax_kernel<<<nRows, 256>>>(sc);
    pv_kernel<<<gPV, 256, PV_SMEM>>>(sc, v, att);
    mma_gemm<false,true><<<gDD, 128, GEMM_SMEM>>>(att, sa_o, hid, h, TOK, DMODEL, DMODEL);

    // ---- Cross-attention ----
    rms_kernel<<<TOK, 256>>>(h, ln2_w, xn);
    mma_gemm<false,false><<<gDD, 128, GEMM_SMEM>>>(xn,  ca_q, nullptr, q, TOK, DMODEL, DMODEL);
    mma_gemm<false,false><<<gDD, 128, GEMM_SMEM>>>(enc, ca_k, nullptr, k, TOK, DMODEL, DMODEL);
    mma_gemm<false,false><<<gDD, 128, GEMM_SMEM>>>(enc, ca_v, nullptr, v, TOK, DMODEL, DMODEL);
    scores_kernel<false><<<gScore, 256, SC_SMEM>>>(q, k, nullptr, emask, sc);
    softmax_kernel<<<nRows, 256>>>(sc);
    pv_kernel<<<gPV, 256, PV_SMEM>>>(sc, v, att);
    mma_gemm<false,true><<<gDD, 128, GEMM_SMEM>>>(att, ca_o, h, h, TOK, DMODEL, DMODEL);

    // ---- FFN ----
    rms_kernel<<<TOK, 256>>>(h, ln3_w, xn);
    mma_gemm<true,false><<<gDF, 128, GEMM_SMEM>>>(xn, wi, nullptr, ffn, TOK, DFF, DMODEL);
    mma_gemm<false,true><<<gDD, 128, GEMM_SMEM>>>(ffn, wo, h, h, TOK, DMODEL, DFF);

    // ---- Final norm ----
    rms_kernel<<<TOK, 256>>>(h, flnw, out);
}

// round 5
// speedup vs baseline: 3.3150x; 1.0543x over previous
#include <cuda_runtime.h>
#include <math.h>
#include <stdint.h>

// ---------------- Problem constants ----------------
#define BATCH 4
#define LSEQ  1024
#define DMODEL 1024
#define HEADS 16
#define DKV   64
#define DFF   4096
#define TOK   (BATCH * LSEQ)
#define NBUCK 32
#define NEGINF (-1e9f)

// ---------------- Scratch ----------------
__device__ float g_xnorm[TOK * DMODEL];
__device__ float g_q[TOK * DMODEL];
__device__ float g_k[TOK * DMODEL];
__device__ float g_v[TOK * DMODEL];
__device__ float g_att[TOK * DMODEL];
__device__ float g_h[TOK * DMODEL];
__device__ float g_encr[TOK * DMODEL];     // tf32-rounded encoder states
__device__ float g_ffn[TOK * DFF];
__device__ float g_scores[(size_t)BATCH * HEADS * LSEQ * LSEQ];
__device__ float g_wr[16 * 1024 * 1024];   // tf32-rounded weights (orig layout)
__device__ int   g_bucket[LSEQ];

#define WR_SAQ 0
#define WR_SAK (1 * 1048576)
#define WR_SAV (2 * 1048576)
#define WR_SAO (3 * 1048576)
#define WR_CAQ (4 * 1048576)
#define WR_CAK (5 * 1048576)
#define WR_CAV (6 * 1048576)
#define WR_CAO (7 * 1048576)
#define WR_WI  (8 * 1048576)
#define WR_WO  (12 * 1048576)

// ---------------- helpers ----------------
__device__ __forceinline__ float f2tf32(float x) {
    uint32_t r;
    asm("cvt.rna.tf32.f32 %0, %1;" : "=r"(r) : "f"(x));
    return __uint_as_float(r);
}
__device__ __forceinline__ uint32_t ldsu(const float* p) {
    return __float_as_uint(*p);
}
__device__ __forceinline__ void mma_tf32(float (&d)[4], const uint32_t (&a)[4],
                                         const uint32_t (&b)[2]) {
    asm volatile(
        "mma.sync.aligned.m16n8k8.row.col.f32.tf32.tf32.f32 "
        "{%0,%1,%2,%3}, {%4,%5,%6,%7}, {%8,%9}, {%0,%1,%2,%3};"
        : "+f"(d[0]), "+f"(d[1]), "+f"(d[2]), "+f"(d[3])
        : "r"(a[0]), "r"(a[1]), "r"(a[2]), "r"(a[3]), "r"(b[0]), "r"(b[1]));
}
__device__ __forceinline__ void cp16(float* dst, const float* src) {
    uint32_t d = (uint32_t)__cvta_generic_to_shared(dst);
    asm volatile("cp.async.cg.shared.global [%0], [%1], 16;" :: "r"(d), "l"(src));
}
__device__ __forceinline__ void cp_commit() { asm volatile("cp.async.commit_group;"); }
__device__ __forceinline__ void cp_wait0()  { asm volatile("cp.async.wait_group 0;" ::: "memory"); }

// ---------------- elementwise tf32 round-copy ----------------
__global__ void round_copy(const float* __restrict__ src,
                           float* __restrict__ dst, int n4) {
    int i = blockIdx.x * 256 + threadIdx.x;
    if (i < n4) {
        float4 v = ((const float4*)src)[i];
        v.x = f2tf32(v.x); v.y = f2tf32(v.y);
        v.z = f2tf32(v.z); v.w = f2tf32(v.w);
        ((float4*)dst)[i] = v;
    }
}

// ---------------- RMS norm (optionally tf32-round output) -----------------
template<bool ROUND>
__global__ void rms_kernel(const float* __restrict__ x,
                           const float* __restrict__ w,
                           float* __restrict__ y) {
    int row = blockIdx.x;
    const float* xr = x + (size_t)row * DMODEL;
    float s = 0.f;
    for (int i = threadIdx.x; i < DMODEL; i += 256) {
        float v = xr[i];
        s += v * v;
    }
    __shared__ float red[8];
    #pragma unroll
    for (int o = 16; o; o >>= 1) s += __shfl_xor_sync(0xffffffffu, s, o);
    if ((threadIdx.x & 31) == 0) red[threadIdx.x >> 5] = s;
    __syncthreads();
    if (threadIdx.x < 8) {
        float t = red[threadIdx.x];
        #pragma unroll
        for (int o = 4; o; o >>= 1) t += __shfl_xor_sync(0xffu, t, o);
        if (threadIdx.x == 0) red[0] = rsqrtf(t * (1.0f / DMODEL) + 1e-6f);
    }
    __syncthreads();
    float inv = red[0];
    float* yr = y + (size_t)row * DMODEL;
    for (int i = threadIdx.x; i < DMODEL; i += 256) {
        float v = xr[i] * inv * w[i];
        yr[i] = ROUND ? f2tf32(v) : v;
    }
}

// ---------------- tf32 GEMM: C[M,N]=A@B (+R)(ReLU)(ROUND) -----------------
// Block 128x128x32, 128 threads = 4 warps (2x2), warp tile 64x64.
// All operands pre-rounded tf32: plain LDS feeds MMA. Fragment double-buffer.
#define GA_S 36
#define GB_S 136
#define A_STG (128 * GA_S)
#define B_STG (32 * GB_S)
#define GEMM_SMEM ((2 * A_STG + 2 * B_STG) * 4)

template<bool RELU, bool RES, bool ROUND>
__global__ void __launch_bounds__(128, 2)
mma_gemm(const float* __restrict__ A, const float* __restrict__ B,
         const float* __restrict__ R, float* __restrict__ C,
         int M, int N, int K) {
    extern __shared__ float sm[];
    float* Asm = sm;
    float* Bsm = sm + 2 * A_STG;
    const int tid = threadIdx.x;
    const int warp = tid >> 5, lane = tid & 31;
    const int gid = lane >> 2, tg = lane & 3;
    const int wm = warp & 1, wn = warp >> 1;
    const int m0 = blockIdx.y * 128, n0 = blockIdx.x * 128;

    float acc[4][8][4];
    #pragma unroll
    for (int i = 0; i < 4; i++)
        #pragma unroll
        for (int j = 0; j < 8; j++)
            #pragma unroll
            for (int l = 0; l < 4; l++) acc[i][j][l] = 0.f;

    const float* Ag = A + (size_t)m0 * K;
    const float* Bg = B + n0;

    #define LOAD_TILE(kt, s) do {                                              \
        float* ad = Asm + (s) * A_STG;                                         \
        float* bd = Bsm + (s) * B_STG;                                         \
        _Pragma("unroll")                                                      \
        for (int i = 0; i < 8; i++) {                                          \
            int idx = tid + i * 128;                                           \
            int am = idx >> 3, akv = (idx & 7) << 2;                           \
            cp16(ad + am * GA_S + akv, Ag + (size_t)am * K + (kt) + akv);      \
            int bk = idx >> 5, bnv = (idx & 31) << 2;                          \
            cp16(bd + bk * GB_S + bnv, Bg + (size_t)((kt) + bk) * N + bnv);    \
        }                                                                      \
        cp_commit();                                                           \
    } while (0)

    #define LOAD_FRAG(Ab, Bb, kk, af, bf) do {                                 \
        _Pragma("unroll")                                                      \
        for (int mf = 0; mf < 4; mf++) {                                       \
            int m = wm * 64 + mf * 16 + gid;                                   \
            (af)[mf][0] = ldsu((Ab) + m * GA_S + (kk) + tg);                   \
            (af)[mf][1] = ldsu((Ab) + (m + 8) * GA_S + (kk) + tg);             \
            (af)[mf][2] = ldsu((Ab) + m * GA_S + (kk) + tg + 4);               \
            (af)[mf][3] = ldsu((Ab) + (m + 8) * GA_S + (kk) + tg + 4);         \
        }                                                                      \
        _Pragma("unroll")                                                      \
        for (int nf = 0; nf < 8; nf++) {                                       \
            int n = wn * 64 + nf * 8 + gid;                                    \
            (bf)[nf][0] = ldsu((Bb) + ((kk) + tg) * GB_S + n);                 \
            (bf)[nf][1] = ldsu((Bb) + ((kk) + tg + 4) * GB_S + n);             \
        }                                                                      \
    } while (0)

    LOAD_TILE(0, 0);
    cp_wait0();
    __syncthreads();

    int s = 0;
    for (int kt = 0; kt < K; kt += 32) {
        bool more = (kt + 32 < K);
        if (more) LOAD_TILE(kt + 32, s ^ 1);
        const float* Ab = Asm + s * A_STG;
        const float* Bb = Bsm + s * B_STG;
        uint32_t af[2][4][4], bf[2][8][2];
        LOAD_FRAG(Ab, Bb, 0, af[0], bf[0]);
        #pragma unroll
        for (int ks = 0; ks < 4; ks++) {
            int cur = ks & 1;
            if (ks < 3) LOAD_FRAG(Ab, Bb, (ks + 1) * 8, af[cur ^ 1], bf[cur ^ 1]);
            #pragma unroll
            for (int mf = 0; mf < 4; mf++)
                #pragma unroll
                for (int nf = 0; nf < 8; nf++)
                    mma_tf32(acc[mf][nf], af[cur][mf], bf[cur][nf]);
        }
        if (more) cp_wait0();
        __syncthreads();
        s ^= 1;
    }

    #pragma unroll
    for (int mf = 0; mf < 4; mf++) {
        #pragma unroll
        for (int nf = 0; nf < 8; nf++) {
            int r0 = m0 + wm * 64 + mf * 16 + gid;
            int c  = n0 + wn * 64 + nf * 8 + tg * 2;
            float2 v0 = make_float2(acc[mf][nf][0], acc[mf][nf][1]);
            float2 v1 = make_float2(acc[mf][nf][2], acc[mf][nf][3]);
            if (RES) {
                float2 a0 = *(const float2*)(R + (size_t)r0 * N + c);
                float2 a1 = *(const float2*)(R + (size_t)(r0 + 8) * N + c);
                v0.x += a0.x; v0.y += a0.y; v1.x += a1.x; v1.y += a1.y;
            }
            if (RELU) {
                v0.x = fmaxf(v0.x, 0.f); v0.y = fmaxf(v0.y, 0.f);
                v1.x = fmaxf(v1.x, 0.f); v1.y = fmaxf(v1.y, 0.f);
            }
            if (ROUND) {
                v0.x = f2tf32(v0.x); v0.y = f2tf32(v0.y);
                v1.x = f2tf32(v1.x); v1.y = f2tf32(v1.y);
            }
            *(float2*)(C + (size_t)r0 * N + c) = v0;
            *(float2*)(C + (size_t)(r0 + 8) * N + c) = v1;
        }
    }
    #undef LOAD_TILE
    #undef LOAD_FRAG
}

// ---------------- T5 relative bucket table ----------------
__global__ void bucket_kernel() {
    int n = threadIdx.x;
    int b;
    if (n < 16) {
        b = n;
    } else {
        float nf = (float)n;
        int vl = 16 + (int)(logf(nf / 16.0f) / logf(8.0f) * 16.0f);
        b = vl < (NBUCK - 1) ? vl : (NBUCK - 1);
    }
    g_bucket[n] = b;
}

// ---------------- Attention scores ----------------
// Block 128x128 tile of one (b,h), 256 threads = 8 warps (2M x 4N), warp 64x32.
#define SC_S 68
#define SC_SMEM ((128 * SC_S * 2) * 4)

template<bool SELF>
__global__ void __launch_bounds__(256)
scores_kernel(const float* __restrict__ Q, const float* __restrict__ KV,
              const float* __restrict__ relb, const int* __restrict__ mask,
              float* __restrict__ S) {
    extern __shared__ float sm[];
    float* Qs = sm;
    float* Ks = sm + 128 * SC_S;
    int tid = threadIdx.x;
    int warp = tid >> 5, lane = tid & 31;
    int gid = lane >> 2, tg = lane & 3;
    int wm = warp & 1, wn = warp >> 1;
    int k0 = blockIdx.x * 128, q0 = blockIdx.y * 128;
    int bh = blockIdx.z;
    int b = bh >> 4, h = bh & 15;

    #pragma unroll
    for (int i = 0; i < 8; i++) {
        int idx = tid + i * 256;
        int row = idx >> 4, cv = (idx & 15) << 2;
        cp16(Qs + row * SC_S + cv,
             Q + (size_t)(b * LSEQ + q0 + row) * DMODEL + h * DKV + cv);
        cp16(Ks + row * SC_S + cv,
             KV + (size_t)(b * LSEQ + k0 + row) * DMODEL + h * DKV + cv);
    }
    cp_commit();
    cp_wait0();
    __syncthreads();

    float acc[4][4][4];
    #pragma unroll
    for (int i = 0; i < 4; i++)
        #pragma unroll
        for (int j = 0; j < 4; j++)
            #pragma unroll
            for (int l = 0; l < 4; l++) acc[i][j][l] = 0.f;

    #define SC_FRAG(kk, af, bf) do {                                           \
        _Pragma("unroll")                                                      \
        for (int mf = 0; mf < 4; mf++) {                                       \
            int m = wm * 64 + mf * 16 + gid;                                   \
            (af)[mf][0] = ldsu(Qs + m * SC_S + (kk) + tg);                     \
            (af)[mf][1] = ldsu(Qs + (m + 8) * SC_S + (kk) + tg);               \
            (af)[mf][2] = ldsu(Qs + m * SC_S + (kk) + tg + 4);                 \
            (af)[mf][3] = ldsu(Qs + (m + 8) * SC_S + (kk) + tg + 4);           \
        }                                                                      \
        _Pragma("unroll")                                                      \
        for (int nf = 0; nf < 4; nf++) {                                       \
            int n = wn * 32 + nf * 8 + gid;                                    \
            (bf)[nf][0] = ldsu(Ks + n * SC_S + (kk) + tg);                     \
            (bf)[nf][1] = ldsu(Ks + n * SC_S + (kk) + tg + 4);                 \
        }                                                                      \
    } while (0)

    uint32_t af[2][4][4], bf[2][4][2];
    SC_FRAG(0, af[0], bf[0]);
    #pragma unroll
    for (int ks = 0; ks < 8; ks++) {
        int cur = ks & 1;
        if (ks < 7) SC_FRAG((ks + 1) * 8, af[cur ^ 1], bf[cur ^ 1]);
        #pragma unroll
        for (int mf = 0; mf < 4; mf++)
            #pragma unroll
            for (int nf = 0; nf < 4; nf++)
                mma_tf32(acc[mf][nf], af[cur][mf], bf[cur][nf]);
    }
    #undef SC_FRAG

    #pragma unroll
    for (int mf = 0; mf < 4; mf++) {
        #pragma unroll
        for (int nf = 0; nf < 4; nf++) {
            #pragma unroll
            for (int half = 0; half < 2; half++) {
                int qi = q0 + wm * 64 + mf * 16 + gid + half * 8;
                int c  = k0 + wn * 32 + nf * 8 + tg * 2;
                float v0 = acc[mf][nf][half * 2 + 0];
                float v1 = acc[mf][nf][half * 2 + 1];
                if (SELF) {
                    int d0 = qi - c, d1 = qi - (c + 1);
                    v0 += relb[g_bucket[d0 > 0 ? d0 : 0] * HEADS + h];
                    v1 += relb[g_bucket[d1 > 0 ? d1 : 0] * HEADS + h];
                    if (!((c     <= qi) && (mask[b * LSEQ + c    ] > 0))) v0 += NEGINF;
                    if (!((c + 1 <= qi) && (mask[b * LSEQ + c + 1] > 0))) v1 += NEGINF;
                } else {
                    if (!(mask[b * LSEQ + c    ] > 0)) v0 += NEGINF;
                    if (!(mask[b * LSEQ + c + 1] > 0)) v1 += NEGINF;
                }
                *(float2*)(S + ((size_t)bh * LSEQ + qi) * LSEQ + c) = make_float2(v0, v1);
            }
        }
    }
}

// ---------------- Row softmax, in place, tf32-rounded output --------------
__global__ void softmax_kernel(float* __restrict__ S) {
    float* p = S + (size_t)blockIdx.x * LSEQ;
    int tid = threadIdx.x;
    float x0 = p[tid], x1 = p[tid + 256], x2 = p[tid + 512], x3 = p[tid + 768];
    float m = fmaxf(fmaxf(x0, x1), fmaxf(x2, x3));
    __shared__ float red[8];
    #pragma unroll
    for (int o = 16; o; o >>= 1) m = fmaxf(m, __shfl_xor_sync(0xffffffffu, m, o));
    if ((tid & 31) == 0) red[tid >> 5] = m;
    __syncthreads();
    if (tid < 8) {
        float t = red[tid];
        #pragma unroll
        for (int o = 4; o; o >>= 1) t = fmaxf(t, __shfl_xor_sync(0xffu, t, o));
        if (tid == 0) red[0] = t;
    }
    __syncthreads();
    m = red[0];
    __syncthreads();
    float e0 = __expf(x0 - m), e1 = __expf(x1 - m), e2 = __expf(x2 - m), e3 = __expf(x3 - m);
    float s = e0 + e1 + e2 + e3;
    #pragma unroll
    for (int o = 16; o; o >>= 1) s += __shfl_xor_sync(0xffffffffu, s, o);
    if ((tid & 31) == 0) red[tid >> 5] = s;
    __syncthreads();
    if (tid < 8) {
        float t = red[tid];
        #pragma unroll
        for (int o = 4; o; o >>= 1) t += __shfl_xor_sync(0xffu, t, o);
        if (tid == 0) red[0] = 1.0f / t;
    }
    __syncthreads();
    float inv = red[0];
    p[tid]       = f2tf32(e0 * inv);
    p[tid + 256] = f2tf32(e1 * inv);
    p[tid + 512] = f2tf32(e2 * inv);
    p[tid + 768] = f2tf32(e3 * inv);
}

// ---------------- PV: O = P @ V (P,V pre-rounded) --------------------------
#define PV_PS 36
#define PV_VS 72
#define P_STG (128 * PV_PS)
#define V_STG (32 * PV_VS)
#define PV_SMEM ((2 * P_STG + 2 * V_STG) * 4)

__global__ void __launch_bounds__(256)
pv_kernel(const float* __restrict__ P, const float* __restrict__ V,
          float* __restrict__ O) {
    extern __shared__ float sm[];
    float* Psm = sm;
    float* Vsm = sm + 2 * P_STG;
    int tid = threadIdx.x;
    int warp = tid >> 5, lane = tid & 31;
    int gid = lane >> 2, tg = lane & 3;
    int wm = warp & 3, wn = warp >> 2;
    int q0 = blockIdx.x * 128;
    int bh = blockIdx.y;
    int b = bh >> 4, h = bh & 15;
    const float* Pb = P + ((size_t)bh * LSEQ + q0) * LSEQ;
    const float* Vb = V + (size_t)(b * LSEQ) * DMODEL + h * DKV;

    float acc[2][4][4];
    #pragma unroll
    for (int i = 0; i < 2; i++)
        #pragma unroll
        for (int j = 0; j < 4; j++)
            #pragma unroll
            for (int l = 0; l < 4; l++) acc[i][j][l] = 0.f;

    #define PV_LOAD(kt, s) do {                                               \
        float* pd = Psm + (s) * P_STG;                                        \
        float* vd = Vsm + (s) * V_STG;                                        \
        _Pragma("unroll")                                                     \
        for (int i = 0; i < 4; i++) {                                         \
            int idx = tid + i * 256;                                          \
            int row = idx >> 3, cv = (idx & 7) << 2;                          \
            cp16(pd + row * PV_PS + cv, Pb + (size_t)row * LSEQ + (kt) + cv); \
        }                                                                     \
        _Pragma("unroll")                                                     \
        for (int i = 0; i < 2; i++) {                                         \
            int idx = tid + i * 256;                                          \
            int kr = idx >> 4, dv = (idx & 15) << 2;                          \
            cp16(vd + kr * PV_VS + dv, Vb + (size_t)((kt) + kr) * DMODEL + dv); \
        }                                                                     \
        cp_commit();                                                          \
    } while (0)

    #define PV_FRAG(Pp, Vp, kk, af, bf) do {                                  \
        _Pragma("unroll")                                                     \
        for (int mf = 0; mf < 2; mf++) {                                      \
            int m = wm * 32 + mf * 16 + gid;                                  \
            (af)[mf][0] = ldsu((Pp) + m * PV_PS + (kk) + tg);                 \
            (af)[mf][1] = ldsu((Pp) + (m + 8) * PV_PS + (kk) + tg);           \
            (af)[mf][2] = ldsu((Pp) + m * PV_PS + (kk) + tg + 4);             \
            (af)[mf][3] = ldsu((Pp) + (m + 8) * PV_PS + (kk) + tg + 4);       \
        }                                                                     \
        _Pragma("unroll")                                                     \
        for (int nf = 0; nf < 4; nf++) {                                      \
            int n = wn * 32 + nf * 8 + gid;                                   \
            (bf)[nf][0] = ldsu((Vp) + ((kk) + tg) * PV_VS + n);               \
            (bf)[nf][1] = ldsu((Vp) + ((kk) + tg + 4) * PV_VS + n);           \
        }                                                                     \
    } while (0)

    PV_LOAD(0, 0);
    cp_wait0();
    __syncthreads();

    int s = 0;
    for (int kt = 0; kt < LSEQ; kt += 32) {
        bool more = (kt + 32 < LSEQ);
        if (more) PV_LOAD(kt + 32, s ^ 1);
        const float* Pp = Psm + s * P_STG;
        const float* Vp = Vsm + s * V_STG;
        uint32_t af[2][2][4], bf[2][4][2];
        PV_FRAG(Pp, Vp, 0, af[0], bf[0]);
        #pragma unroll
        for (int ks = 0; ks < 4; ks++) {
            int cur = ks & 1;
            if (ks < 3) PV_FRAG(Pp, Vp, (ks + 1) * 8, af[cur ^ 1], bf[cur ^ 1]);
            #pragma unroll
            for (int mf = 0; mf < 2; mf++)
                #pragma unroll
                for (int nf = 0; nf < 4; nf++)
                    mma_tf32(acc[mf][nf], af[cur][mf], bf[cur][nf]);
        }
        if (more) cp_wait0();
        __syncthreads();
        s ^= 1;
    }

    // att feeds the next GEMM's A operand -> store tf32-rounded
    #pragma unroll
    for (int mf = 0; mf < 2; mf++) {
        #pragma unroll
        for (int nf = 0; nf < 4; nf++) {
            int r0 = q0 + wm * 32 + mf * 16 + gid;
            int c  = wn * 32 + nf * 8 + tg * 2;
            *(float2*)(O + (size_t)(b * LSEQ + r0) * DMODEL + h * DKV + c)
                = make_float2(f2tf32(acc[mf][nf][0]), f2tf32(acc[mf][nf][1]));
            *(float2*)(O + (size_t)(b * LSEQ + r0 + 8) * DMODEL + h * DKV + c)
                = make_float2(f2tf32(acc[mf][nf][2]), f2tf32(acc[mf][nf][3]));
        }
    }
    #undef PV_LOAD
    #undef PV_FRAG
}

// ---------------- Orchestration -------------------------------------------
extern "C" void kernel_launch(void* const* d_in, const int* in_sizes, int n_in,
                              void* d_out, int out_size) {
    const float* enc    = (const float*)d_in[0];
    const float* hid    = (const float*)d_in[1];
    const float* ln1_w  = (const float*)d_in[2];
    const float* sa_q   = (const float*)d_in[3];
    const float* sa_k   = (const float*)d_in[4];
    const float* sa_v   = (const float*)d_in[5];
    const float* sa_o   = (const float*)d_in[6];
    const float* relb   = (const float*)d_in[7];
    const float* ln2_w  = (const float*)d_in[8];
    const float* ca_q   = (const float*)d_in[9];
    const float* ca_k   = (const float*)d_in[10];
    const float* ca_v   = (const float*)d_in[11];
    const float* ca_o   = (const float*)d_in[12];
    const float* ln3_w  = (const float*)d_in[13];
    const float* wi     = (const float*)d_in[14];
    const float* wo     = (const float*)d_in[15];
    const float* flnw   = (const float*)d_in[16];
    const int*   emask  = (const int*)d_in[17];
    const int*   dmask  = (const int*)d_in[18];
    float* out = (float*)d_out;

    float *xn, *q, *k, *v, *att, *h, *ffn, *sc, *wr, *encr;
    cudaGetSymbolAddress((void**)&xn,   g_xnorm);
    cudaGetSymbolAddress((void**)&q,    g_q);
    cudaGetSymbolAddress((void**)&k,    g_k);
    cudaGetSymbolAddress((void**)&v,    g_v);
    cudaGetSymbolAddress((void**)&att,  g_att);
    cudaGetSymbolAddress((void**)&h,    g_h);
    cudaGetSymbolAddress((void**)&ffn,  g_ffn);
    cudaGetSymbolAddress((void**)&sc,   g_scores);
    cudaGetSymbolAddress((void**)&wr,   g_wr);
    cudaGetSymbolAddress((void**)&encr, g_encr);

    cudaFuncSetAttribute(mma_gemm<false,false,true>,  cudaFuncAttributeMaxDynamicSharedMemorySize, GEMM_SMEM);
    cudaFuncSetAttribute(mma_gemm<false,true,false>,  cudaFuncAttributeMaxDynamicSharedMemorySize, GEMM_SMEM);
    cudaFuncSetAttribute(mma_gemm<true,false,true>,   cudaFuncAttributeMaxDynamicSharedMemorySize, GEMM_SMEM);
    cudaFuncSetAttribute(scores_kernel<true>,   cudaFuncAttributeMaxDynamicSharedMemorySize, SC_SMEM);
    cudaFuncSetAttribute(scores_kernel<false>,  cudaFuncAttributeMaxDynamicSharedMemorySize, SC_SMEM);
    cudaFuncSetAttribute(pv_kernel,             cudaFuncAttributeMaxDynamicSharedMemorySize, PV_SMEM);

    // ---- pre-round weights (original layout) + encoder states ----
    int n4_dd = DMODEL * DMODEL / 4, n4_df = DMODEL * DFF / 4, n4_tok = TOK * DMODEL / 4;
    round_copy<<<(n4_dd + 255) / 256, 256>>>(sa_q, wr + WR_SAQ, n4_dd);
    round_copy<<<(n4_dd + 255) / 256, 256>>>(sa_k, wr + WR_SAK, n4_dd);
    round_copy<<<(n4_dd + 255) / 256, 256>>>(sa_v, wr + WR_SAV, n4_dd);
    round_copy<<<(n4_dd + 255) / 256, 256>>>(sa_o, wr + WR_SAO, n4_dd);
    round_copy<<<(n4_dd + 255) / 256, 256>>>(ca_q, wr + WR_CAQ, n4_dd);
    round_copy<<<(n4_dd + 255) / 256, 256>>>(ca_k, wr + WR_CAK, n4_dd);
    round_copy<<<(n4_dd + 255) / 256, 256>>>(ca_v, wr + WR_CAV, n4_dd);
    round_copy<<<(n4_dd + 255) / 256, 256>>>(ca_o, wr + WR_CAO, n4_dd);
    round_copy<<<(n4_df + 255) / 256, 256>>>(wi,   wr + WR_WI,  n4_df);
    round_copy<<<(n4_df + 255) / 256, 256>>>(wo,   wr + WR_WO,  n4_df);
    round_copy<<<(n4_tok + 255) / 256, 256>>>(enc, encr, n4_tok);

    dim3 gDD(DMODEL / 128, TOK / 128);
    dim3 gDF(DFF / 128, TOK / 128);
    dim3 gScore(8, 8, BATCH * HEADS);
    dim3 gPV(8, BATCH * HEADS);
    int nRows = BATCH * HEADS * LSEQ;

    bucket_kernel<<<1, 1024>>>();

    // ---- Self-attention ----
    rms_kernel<true><<<TOK, 256>>>(hid, ln1_w, xn);
    mma_gemm<false,false,true><<<gDD, 128, GEMM_SMEM>>>(xn, wr + WR_SAQ, nullptr, q, TOK, DMODEL, DMODEL);
    mma_gemm<false,false,true><<<gDD, 128, GEMM_SMEM>>>(xn, wr + WR_SAK, nullptr, k, TOK, DMODEL, DMODEL);
    mma_gemm<false,false,true><<<gDD, 128, GEMM_SMEM>>>(xn, wr + WR_SAV, nullptr, v, TOK, DMODEL, DMODEL);
    scores_kernel<true><<<gScore, 256, SC_SMEM>>>(q, k, relb, dmask, sc);
    softmax_kernel<<<nRows, 256>>>(sc);
    pv_kernel<<<gPV, 256, PV_SMEM>>>(sc, v, att);
    mma_gemm<false,true,false><<<gDD, 128, GEMM_SMEM>>>(att, wr + WR_SAO, hid, h, TOK, DMODEL, DMODEL);

    // ---- Cross-attention ----
    rms_kernel<true><<<TOK, 256>>>(h, ln2_w, xn);
    mma_gemm<false,false,true><<<gDD, 128, GEMM_SMEM>>>(xn,   wr + WR_CAQ, nullptr, q, TOK, DMODEL, DMODEL);
    mma_gemm<false,false,true><<<gDD, 128, GEMM_SMEM>>>(encr, wr + WR_CAK, nullptr, k, TOK, DMODEL, DMODEL);
    mma_gemm<false,false,true><<<gDD, 128, GEMM_SMEM>>>(encr, wr + WR_CAV, nullptr, v, TOK, DMODEL, DMODEL);
    scores_kernel<false><<<gScore, 256, SC_SMEM>>>(q, k, nullptr, emask, sc);
    softmax_kernel<<<nRows, 256>>>(sc);
    pv_kernel<<<gPV, 256, PV_SMEM>>>(sc, v, att);
    mma_gemm<false,true,false><<<gDD, 128, GEMM_SMEM>>>(att, wr + WR_CAO, h, h, TOK, DMODEL, DMODEL);

    // ---- FFN ----
    rms_kernel<true><<<TOK, 256>>>(h, ln3_w, xn);
    mma_gemm<true,false,true><<<gDF, 128, GEMM_SMEM>>>(xn, wr + WR_WI, nullptr, ffn, TOK, DFF, DMODEL);
    mma_gemm<false,true,false><<<gDD, 128, GEMM_SMEM>>>(ffn, wr + WR_WO, h, h, TOK, DMODEL, DFF);

    // ---- Final norm ----
    rms_kernel<false><<<TOK, 256>>>(h, flnw, out);
}

// round 6
// speedup vs baseline: 3.9019x; 1.1771x over previous
#include <cuda_runtime.h>
#include <math.h>
#include <stdint.h>

// ---------------- Problem constants ----------------
#define BATCH 4
#define LSEQ  1024
#define DMODEL 1024
#define HEADS 16
#define DKV   64
#define DFF   4096
#define TOK   (BATCH * LSEQ)
#define NBUCK 32
#define NEGINF (-1e9f)

// ---------------- Scratch ----------------
__device__ float g_xnorm[TOK * DMODEL];
__device__ float g_qkv[TOK * 3072];        // self: fused QKV; cross: Q (first 1024 cols used as [TOK][1024])
__device__ float g_kvx[TOK * 2048];        // cross: fused KV
__device__ float g_att[TOK * DMODEL];
__device__ float g_h[TOK * DMODEL];
__device__ float g_encr[TOK * DMODEL];     // tf32-rounded encoder states
__device__ float g_ffn[TOK * DFF];
__device__ float g_wr[16 * 1024 * 1024];   // tf32-rounded weights
__device__ int   g_bucket[LSEQ];

#define WR_QKV 0                       // [1024][3072]
#define WR_CAQ (3 * 1048576)           // [1024][1024]
#define WR_KVX (4 * 1048576)           // [1024][2048]
#define WR_SAO (6 * 1048576)
#define WR_CAO (7 * 1048576)
#define WR_WI  (8 * 1048576)
#define WR_WO  (12 * 1048576)

// ---------------- helpers ----------------
__device__ __forceinline__ float f2tf32(float x) {
    uint32_t r;
    asm("cvt.rna.tf32.f32 %0, %1;" : "=r"(r) : "f"(x));
    return __uint_as_float(r);
}
__device__ __forceinline__ uint32_t ldsu(const float* p) {
    return __float_as_uint(*p);
}
__device__ __forceinline__ void mma_tf32(float (&d)[4], const uint32_t (&a)[4],
                                         const uint32_t (&b)[2]) {
    asm volatile(
        "mma.sync.aligned.m16n8k8.row.col.f32.tf32.tf32.f32 "
        "{%0,%1,%2,%3}, {%4,%5,%6,%7}, {%8,%9}, {%0,%1,%2,%3};"
        : "+f"(d[0]), "+f"(d[1]), "+f"(d[2]), "+f"(d[3])
        : "r"(a[0]), "r"(a[1]), "r"(a[2]), "r"(a[3]), "r"(b[0]), "r"(b[1]));
}
__device__ __forceinline__ void cp16(float* dst, const float* src) {
    uint32_t d = (uint32_t)__cvta_generic_to_shared(dst);
    asm volatile("cp.async.cg.shared.global [%0], [%1], 16;" :: "r"(d), "l"(src));
}
__device__ __forceinline__ void cp_commit() { asm volatile("cp.async.commit_group;"); }
__device__ __forceinline__ void cp_wait0()  { asm volatile("cp.async.wait_group 0;" ::: "memory"); }

// ---------------- pre-processing kernels ----------------
__global__ void round_copy(const float* __restrict__ src,
                           float* __restrict__ dst, int n4) {
    int i = blockIdx.x * 256 + threadIdx.x;
    if (i < n4) {
        float4 v = ((const float4*)src)[i];
        v.x = f2tf32(v.x); v.y = f2tf32(v.y);
        v.z = f2tf32(v.z); v.w = f2tf32(v.w);
        ((float4*)dst)[i] = v;
    }
}

// dst[k][0..3071] = round([a|b|c]) ; each source [1024][1024]
__global__ void concat3_round(const float* __restrict__ a, const float* __restrict__ b,
                              const float* __restrict__ c, float* __restrict__ dst) {
    int i = blockIdx.x * 256 + threadIdx.x;     // float4 index; total 1024*768
    if (i >= 1024 * 768) return;
    int row = i / 768, c4 = i % 768;
    const float* src = (c4 < 256) ? a : ((c4 < 512) ? b : c);
    int cc = c4 & 255;
    float4 v = ((const float4*)(src + (size_t)row * 1024))[cc];
    v.x = f2tf32(v.x); v.y = f2tf32(v.y); v.z = f2tf32(v.z); v.w = f2tf32(v.w);
    ((float4*)(dst + (size_t)row * 3072))[c4] = v;
}

// dst[k][0..2047] = round([a|b])
__global__ void concat2_round(const float* __restrict__ a, const float* __restrict__ b,
                              float* __restrict__ dst) {
    int i = blockIdx.x * 256 + threadIdx.x;     // total 1024*512
    if (i >= 1024 * 512) return;
    int row = i / 512, c4 = i % 512;
    const float* src = (c4 < 256) ? a : b;
    int cc = c4 & 255;
    float4 v = ((const float4*)(src + (size_t)row * 1024))[cc];
    v.x = f2tf32(v.x); v.y = f2tf32(v.y); v.z = f2tf32(v.z); v.w = f2tf32(v.w);
    ((float4*)(dst + (size_t)row * 2048))[c4] = v;
}

// ---------------- RMS norm ----------------
template<bool ROUND>
__global__ void rms_kernel(const float* __restrict__ x,
                           const float* __restrict__ w,
                           float* __restrict__ y) {
    int row = blockIdx.x;
    const float* xr = x + (size_t)row * DMODEL;
    float s = 0.f;
    for (int i = threadIdx.x; i < DMODEL; i += 256) {
        float v = xr[i];
        s += v * v;
    }
    __shared__ float red[8];
    #pragma unroll
    for (int o = 16; o; o >>= 1) s += __shfl_xor_sync(0xffffffffu, s, o);
    if ((threadIdx.x & 31) == 0) red[threadIdx.x >> 5] = s;
    __syncthreads();
    if (threadIdx.x < 8) {
        float t = red[threadIdx.x];
        #pragma unroll
        for (int o = 4; o; o >>= 1) t += __shfl_xor_sync(0xffu, t, o);
        if (threadIdx.x == 0) red[0] = rsqrtf(t * (1.0f / DMODEL) + 1e-6f);
    }
    __syncthreads();
    float inv = red[0];
    float* yr = y + (size_t)row * DMODEL;
    for (int i = threadIdx.x; i < DMODEL; i += 256) {
        float v = xr[i] * inv * w[i];
        yr[i] = ROUND ? f2tf32(v) : v;
    }
}

// ---------------- tf32 GEMM (pre-rounded operands) ------------------------
#define GA_S 36
#define GB_S 136
#define A_STG (128 * GA_S)
#define B_STG (32 * GB_S)
#define GEMM_SMEM ((2 * A_STG + 2 * B_STG) * 4)

template<bool RELU, bool RES, bool ROUND>
__global__ void __launch_bounds__(128, 2)
mma_gemm(const float* __restrict__ A, const float* __restrict__ B,
         const float* __restrict__ R, float* __restrict__ C,
         int M, int N, int K) {
    extern __shared__ float sm[];
    float* Asm = sm;
    float* Bsm = sm + 2 * A_STG;
    const int tid = threadIdx.x;
    const int warp = tid >> 5, lane = tid & 31;
    const int gid = lane >> 2, tg = lane & 3;
    const int wm = warp & 1, wn = warp >> 1;
    const int m0 = blockIdx.y * 128, n0 = blockIdx.x * 128;

    float acc[4][8][4];
    #pragma unroll
    for (int i = 0; i < 4; i++)
        #pragma unroll
        for (int j = 0; j < 8; j++)
            #pragma unroll
            for (int l = 0; l < 4; l++) acc[i][j][l] = 0.f;

    const float* Ag = A + (size_t)m0 * K;
    const float* Bg = B + n0;

    #define LOAD_TILE(kt, s) do {                                              \
        float* ad = Asm + (s) * A_STG;                                         \
        float* bd = Bsm + (s) * B_STG;                                         \
        _Pragma("unroll")                                                      \
        for (int i = 0; i < 8; i++) {                                          \
            int idx = tid + i * 128;                                           \
            int am = idx >> 3, akv = (idx & 7) << 2;                           \
            cp16(ad + am * GA_S + akv, Ag + (size_t)am * K + (kt) + akv);      \
            int bk = idx >> 5, bnv = (idx & 31) << 2;                          \
            cp16(bd + bk * GB_S + bnv, Bg + (size_t)((kt) + bk) * N + bnv);    \
        }                                                                      \
        cp_commit();                                                           \
    } while (0)

    #define LOAD_FRAG(Ab, Bb, kk, af, bf) do {                                 \
        _Pragma("unroll")                                                      \
        for (int mf = 0; mf < 4; mf++) {                                       \
            int m = wm * 64 + mf * 16 + gid;                                   \
            (af)[mf][0] = ldsu((Ab) + m * GA_S + (kk) + tg);                   \
            (af)[mf][1] = ldsu((Ab) + (m + 8) * GA_S + (kk) + tg);             \
            (af)[mf][2] = ldsu((Ab) + m * GA_S + (kk) + tg + 4);               \
            (af)[mf][3] = ldsu((Ab) + (m + 8) * GA_S + (kk) + tg + 4);         \
        }                                                                      \
        _Pragma("unroll")                                                      \
        for (int nf = 0; nf < 8; nf++) {                                       \
            int n = wn * 64 + nf * 8 + gid;                                    \
            (bf)[nf][0] = ldsu((Bb) + ((kk) + tg) * GB_S + n);                 \
            (bf)[nf][1] = ldsu((Bb) + ((kk) + tg + 4) * GB_S + n);             \
        }                                                                      \
    } while (0)

    LOAD_TILE(0, 0);
    cp_wait0();
    __syncthreads();

    int s = 0;
    for (int kt = 0; kt < K; kt += 32) {
        bool more = (kt + 32 < K);
        if (more) LOAD_TILE(kt + 32, s ^ 1);
        const float* Ab = Asm + s * A_STG;
        const float* Bb = Bsm + s * B_STG;
        uint32_t af[2][4][4], bf[2][8][2];
        LOAD_FRAG(Ab, Bb, 0, af[0], bf[0]);
        #pragma unroll
        for (int ks = 0; ks < 4; ks++) {
            int cur = ks & 1;
            if (ks < 3) LOAD_FRAG(Ab, Bb, (ks + 1) * 8, af[cur ^ 1], bf[cur ^ 1]);
            #pragma unroll
            for (int mf = 0; mf < 4; mf++)
                #pragma unroll
                for (int nf = 0; nf < 8; nf++)
                    mma_tf32(acc[mf][nf], af[cur][mf], bf[cur][nf]);
        }
        if (more) cp_wait0();
        __syncthreads();
        s ^= 1;
    }

    #pragma unroll
    for (int mf = 0; mf < 4; mf++) {
        #pragma unroll
        for (int nf = 0; nf < 8; nf++) {
            int r0 = m0 + wm * 64 + mf * 16 + gid;
            int c  = n0 + wn * 64 + nf * 8 + tg * 2;
            float2 v0 = make_float2(acc[mf][nf][0], acc[mf][nf][1]);
            float2 v1 = make_float2(acc[mf][nf][2], acc[mf][nf][3]);
            if (RES) {
                float2 a0 = *(const float2*)(R + (size_t)r0 * N + c);
                float2 a1 = *(const float2*)(R + (size_t)(r0 + 8) * N + c);
                v0.x += a0.x; v0.y += a0.y; v1.x += a1.x; v1.y += a1.y;
            }
            if (RELU) {
                v0.x = fmaxf(v0.x, 0.f); v0.y = fmaxf(v0.y, 0.f);
                v1.x = fmaxf(v1.x, 0.f); v1.y = fmaxf(v1.y, 0.f);
            }
            if (ROUND) {
                v0.x = f2tf32(v0.x); v0.y = f2tf32(v0.y);
                v1.x = f2tf32(v1.x); v1.y = f2tf32(v1.y);
            }
            *(float2*)(C + (size_t)r0 * N + c) = v0;
            *(float2*)(C + (size_t)(r0 + 8) * N + c) = v1;
        }
    }
    #undef LOAD_TILE
    #undef LOAD_FRAG
}

// ---------------- T5 relative bucket table ----------------
__global__ void bucket_kernel() {
    int n = threadIdx.x;
    int b;
    if (n < 16) {
        b = n;
    } else {
        float nf = (float)n;
        int vl = 16 + (int)(logf(nf / 16.0f) / logf(8.0f) * 16.0f);
        b = vl < (NBUCK - 1) ? vl : (NBUCK - 1);
    }
    g_bucket[n] = b;
}

// ---------------- Fused flash attention ----------------
// Per CTA: one (b,h), one 128-row q tile. 256 threads = 8 warps.
// QK layout: warps 2M x 4N, tile 64x32. PV layout: warps 4M x 2N, tile 32x32.
// Online softmax stats (running max/sum) in smem; P bounced through smem.
#define FQ_S 68
#define FV_S 72
#define FP_S 132
#define FL_SMEM ((128 * FQ_S * 2 + 128 * FV_S + 128 * FP_S + 512 + 512 + 256 + 128) * 4)

template<bool SELF>
__global__ void __launch_bounds__(256)
flash_kernel(const float* __restrict__ Qp, int qstride,
             const float* __restrict__ Kp, int kstride,
             const float* __restrict__ Vp, int vstride,
             const float* __restrict__ relb, const int* __restrict__ mask,
             float* __restrict__ O) {
    extern __shared__ float sm[];
    float* Qs    = sm;                      // [128][68]
    float* Ks    = Qs + 128 * FQ_S;         // [128][68]
    float* Vs    = Ks + 128 * FQ_S;         // [128][72]  ([k][d])
    float* Ps    = Vs + 128 * FV_S;         // [128][132] ([q][k])
    float* mpart = Ps + 128 * FP_S;         // [128][4]
    float* lpart = mpart + 512;             // [128][4]
    float* mrun  = lpart + 512;             // [2][128]
    float* lrun  = mrun + 256;              // [128]

    int tid = threadIdx.x;
    int warp = tid >> 5, lane = tid & 31;
    int gid = lane >> 2, tg = lane & 3;
    int wm = warp & 1, wn = warp >> 1;      // QK partition
    int pm = warp & 3, pn = warp >> 2;      // PV partition
    int qt = blockIdx.x;
    int q0 = qt * 128;
    int bh = blockIdx.y;
    int b = bh >> 4, h = bh & 15;

    const float* Qg = Qp + (size_t)(b * LSEQ + q0) * qstride + h * DKV;
    const float* Kg = Kp + (size_t)(b * LSEQ) * kstride + h * DKV;
    const float* Vg = Vp + (size_t)(b * LSEQ) * vstride + h * DKV;

    if (tid < 128) { mrun[tid] = -1e30f; lrun[tid] = 0.f; }

    // load Q tile once
    #pragma unroll
    for (int i = 0; i < 8; i++) {
        int idx = tid + i * 256;
        int row = idx >> 4, cv = (idx & 15) << 2;
        cp16(Qs + row * FQ_S + cv, Qg + (size_t)row * qstride + cv);
    }
    cp_commit();

    float oacc[2][4][4];
    #pragma unroll
    for (int i = 0; i < 2; i++)
        #pragma unroll
        for (int j = 0; j < 4; j++)
            #pragma unroll
            for (int l = 0; l < 4; l++) oacc[i][j][l] = 0.f;

    const int niter = SELF ? (qt + 1) : (LSEQ / 128);
    int p = 0;

    for (int it = 0; it < niter; it++) {
        int k0 = it * 128;
        // load K,V tiles
        #pragma unroll
        for (int i = 0; i < 8; i++) {
            int idx = tid + i * 256;
            int row = idx >> 4, cv = (idx & 15) << 2;
            cp16(Ks + row * FQ_S + cv, Kg + (size_t)(k0 + row) * kstride + cv);
            cp16(Vs + row * FV_S + cv, Vg + (size_t)(k0 + row) * vstride + cv);
        }
        cp_commit();
        cp_wait0();
        __syncthreads();

        // ---- QK^T ----
        float sacc[4][4][4];
        #pragma unroll
        for (int i = 0; i < 4; i++)
            #pragma unroll
            for (int j = 0; j < 4; j++)
                #pragma unroll
                for (int l = 0; l < 4; l++) sacc[i][j][l] = 0.f;

        #define FL_QKFRAG(kk, af, bf) do {                                     \
            _Pragma("unroll")                                                  \
            for (int mf = 0; mf < 4; mf++) {                                   \
                int m = wm * 64 + mf * 16 + gid;                               \
                (af)[mf][0] = ldsu(Qs + m * FQ_S + (kk) + tg);                 \
                (af)[mf][1] = ldsu(Qs + (m + 8) * FQ_S + (kk) + tg);           \
                (af)[mf][2] = ldsu(Qs + m * FQ_S + (kk) + tg + 4);             \
                (af)[mf][3] = ldsu(Qs + (m + 8) * FQ_S + (kk) + tg + 4);       \
            }                                                                  \
            _Pragma("unroll")                                                  \
            for (int nf = 0; nf < 4; nf++) {                                   \
                int n = wn * 32 + nf * 8 + gid;                                \
                (bf)[nf][0] = ldsu(Ks + n * FQ_S + (kk) + tg);                 \
                (bf)[nf][1] = ldsu(Ks + n * FQ_S + (kk) + tg + 4);             \
            }                                                                  \
        } while (0)

        {
            uint32_t af[2][4][4], bf[2][4][2];
            FL_QKFRAG(0, af[0], bf[0]);
            #pragma unroll
            for (int ks = 0; ks < 8; ks++) {
                int cur = ks & 1;
                if (ks < 7) FL_QKFRAG((ks + 1) * 8, af[cur ^ 1], bf[cur ^ 1]);
                #pragma unroll
                for (int mf = 0; mf < 4; mf++)
                    #pragma unroll
                    for (int nf = 0; nf < 4; nf++)
                        mma_tf32(sacc[mf][nf], af[cur][mf], bf[cur][nf]);
            }
        }
        #undef FL_QKFRAG

        // ---- bias + mask ----
        bool cok[4][2];
        int ccol[4];
        #pragma unroll
        for (int nf = 0; nf < 4; nf++) {
            int c = k0 + wn * 32 + nf * 8 + tg * 2;
            ccol[nf] = c;
            cok[nf][0] = mask[b * LSEQ + c] > 0;
            cok[nf][1] = mask[b * LSEQ + c + 1] > 0;
        }
        #pragma unroll
        for (int mf = 0; mf < 4; mf++) {
            #pragma unroll
            for (int half = 0; half < 2; half++) {
                int qi = q0 + wm * 64 + mf * 16 + gid + half * 8;
                #pragma unroll
                for (int nf = 0; nf < 4; nf++) {
                    int c = ccol[nf];
                    if (SELF) {
                        int d0 = qi - c, d1 = d0 - 1;
                        sacc[mf][nf][half * 2]     += relb[g_bucket[d0 > 0 ? d0 : 0] * HEADS + h];
                        sacc[mf][nf][half * 2 + 1] += relb[g_bucket[d1 > 0 ? d1 : 0] * HEADS + h];
                        if (!((c     <= qi) && cok[nf][0])) sacc[mf][nf][half * 2]     += NEGINF;
                        if (!((c + 1 <= qi) && cok[nf][1])) sacc[mf][nf][half * 2 + 1] += NEGINF;
                    } else {
                        if (!cok[nf][0]) sacc[mf][nf][half * 2]     += NEGINF;
                        if (!cok[nf][1]) sacc[mf][nf][half * 2 + 1] += NEGINF;
                    }
                }
            }
        }

        // ---- partial row max (within warp, over its 32 cols) ----
        #pragma unroll
        for (int mf = 0; mf < 4; mf++) {
            float mx0 = -1e30f, mx1 = -1e30f;
            #pragma unroll
            for (int nf = 0; nf < 4; nf++) {
                mx0 = fmaxf(mx0, fmaxf(sacc[mf][nf][0], sacc[mf][nf][1]));
                mx1 = fmaxf(mx1, fmaxf(sacc[mf][nf][2], sacc[mf][nf][3]));
            }
            mx0 = fmaxf(mx0, __shfl_xor_sync(0xffffffffu, mx0, 1));
            mx0 = fmaxf(mx0, __shfl_xor_sync(0xffffffffu, mx0, 2));
            mx1 = fmaxf(mx1, __shfl_xor_sync(0xffffffffu, mx1, 1));
            mx1 = fmaxf(mx1, __shfl_xor_sync(0xffffffffu, mx1, 2));
            if (tg == 0) {
                int r0 = wm * 64 + mf * 16 + gid;
                mpart[r0 * 4 + wn] = mx0;
                mpart[(r0 + 8) * 4 + wn] = mx1;
            }
        }
        __syncthreads();

        // ---- m_new, exp, P store, partial sums ----
        float* mold  = mrun + p * 128;
        float* mnewa = mrun + (p ^ 1) * 128;
        #pragma unroll
        for (int mf = 0; mf < 4; mf++) {
            #pragma unroll
            for (int half = 0; half < 2; half++) {
                int r = wm * 64 + mf * 16 + gid + half * 8;
                float mt = fmaxf(fmaxf(mpart[r * 4 + 0], mpart[r * 4 + 1]),
                                 fmaxf(mpart[r * 4 + 2], mpart[r * 4 + 3]));
                float mn = fmaxf(mold[r], mt);
                if (wn == 0 && tg == 0) mnewa[r] = mn;
                float sum = 0.f;
                #pragma unroll
                for (int nf = 0; nf < 4; nf++) {
                    float e0 = __expf(sacc[mf][nf][half * 2]     - mn);
                    float e1 = __expf(sacc[mf][nf][half * 2 + 1] - mn);
                    sum += e0 + e1;
                    int col = wn * 32 + nf * 8 + tg * 2;
                    *(float2*)(Ps + r * FP_S + col) = make_float2(f2tf32(e0), f2tf32(e1));
                }
                sum += __shfl_xor_sync(0xffffffffu, sum, 1);
                sum += __shfl_xor_sync(0xffffffffu, sum, 2);
                if (tg == 0) lpart[r * 4 + wn] = sum;
            }
        }
        __syncthreads();

        // ---- rescale O accumulator, update running sum ----
        #pragma unroll
        for (int mf2 = 0; mf2 < 2; mf2++) {
            #pragma unroll
            for (int half = 0; half < 2; half++) {
                int r = pm * 32 + mf2 * 16 + gid + half * 8;
                float rs = __expf(mold[r] - mnewa[r]);
                #pragma unroll
                for (int nf = 0; nf < 4; nf++) {
                    oacc[mf2][nf][half * 2]     *= rs;
                    oacc[mf2][nf][half * 2 + 1] *= rs;
                }
                if (pn == 0 && tg == 0)
                    lrun[r] = lrun[r] * rs + lpart[r * 4 + 0] + lpart[r * 4 + 1]
                                           + lpart[r * 4 + 2] + lpart[r * 4 + 3];
            }
        }

        // ---- P @ V ----
        #define FL_PVFRAG(kk, af, bf) do {                                     \
            _Pragma("unroll")                                                  \
            for (int mf2 = 0; mf2 < 2; mf2++) {                                \
                int m = pm * 32 + mf2 * 16 + gid;                              \
                (af)[mf2][0] = ldsu(Ps + m * FP_S + (kk) + tg);                \
                (af)[mf2][1] = ldsu(Ps + (m + 8) * FP_S + (kk) + tg);          \
                (af)[mf2][2] = ldsu(Ps + m * FP_S + (kk) + tg + 4);            \
                (af)[mf2][3] = ldsu(Ps + (m + 8) * FP_S + (kk) + tg + 4);      \
            }                                                                  \
            _Pragma("unroll")                                                  \
            for (int nf = 0; nf < 4; nf++) {                                   \
                int n = pn * 32 + nf * 8 + gid;                                \
                (bf)[nf][0] = ldsu(Vs + ((kk) + tg) * FV_S + n);               \
                (bf)[nf][1] = ldsu(Vs + ((kk) + tg + 4) * FV_S + n);           \
            }                                                                  \
        } while (0)

        {
            uint32_t af[2][2][4], bf[2][4][2];
            FL_PVFRAG(0, af[0], bf[0]);
            #pragma unroll
            for (int ks = 0; ks < 16; ks++) {
                int cur = ks & 1;
                if (ks < 15) FL_PVFRAG((ks + 1) * 8, af[cur ^ 1], bf[cur ^ 1]);
                #pragma unroll
                for (int mf2 = 0; mf2 < 2; mf2++)
                    #pragma unroll
                    for (int nf = 0; nf < 4; nf++)
                        mma_tf32(oacc[mf2][nf], af[cur][mf2], bf[cur][nf]);
            }
        }
        #undef FL_PVFRAG

        __syncthreads();
        p ^= 1;
    }

    // ---- normalize and store (tf32-rounded; feeds the next GEMM's A) ----
    #pragma unroll
    for (int mf2 = 0; mf2 < 2; mf2++) {
        int rloc0 = pm * 32 + mf2 * 16 + gid;
        float inv0 = 1.0f / lrun[rloc0];
        float inv1 = 1.0f / lrun[rloc0 + 8];
        #pragma unroll
        for (int nf = 0; nf < 4; nf++) {
            int col = h * DKV + pn * 32 + nf * 8 + tg * 2;
            size_t row0 = (size_t)(b * LSEQ + q0 + rloc0);
            *(float2*)(O + row0 * DMODEL + col)
                = make_float2(f2tf32(oacc[mf2][nf][0] * inv0), f2tf32(oacc[mf2][nf][1] * inv0));
            *(float2*)(O + (row0 + 8) * DMODEL + col)
                = make_float2(f2tf32(oacc[mf2][nf][2] * inv1), f2tf32(oacc[mf2][nf][3] * inv1));
        }
    }
}

// ---------------- Orchestration -------------------------------------------
extern "C" void kernel_launch(void* const* d_in, const int* in_sizes, int n_in,
                              void* d_out, int out_size) {
    const float* enc    = (const float*)d_in[0];
    const float* hid    = (const float*)d_in[1];
    const float* ln1_w  = (const float*)d_in[2];
    const float* sa_q   = (const float*)d_in[3];
    const float* sa_k   = (const float*)d_in[4];
    const float* sa_v   = (const float*)d_in[5];
    const float* sa_o   = (const float*)d_in[6];
    const float* relb   = (const float*)d_in[7];
    const float* ln2_w  = (const float*)d_in[8];
    const float* ca_q   = (const float*)d_in[9];
    const float* ca_k   = (const float*)d_in[10];
    const float* ca_v   = (const float*)d_in[11];
    const float* ca_o   = (const float*)d_in[12];
    const float* ln3_w  = (const float*)d_in[13];
    const float* wi     = (const float*)d_in[14];
    const float* wo     = (const float*)d_in[15];
    const float* flnw   = (const float*)d_in[16];
    const int*   emask  = (const int*)d_in[17];
    const int*   dmask  = (const int*)d_in[18];
    float* out = (float*)d_out;

    float *xn, *qkv, *kvx, *att, *h, *ffn, *wr, *encr;
    cudaGetSymbolAddress((void**)&xn,   g_xnorm);
    cudaGetSymbolAddress((void**)&qkv,  g_qkv);
    cudaGetSymbolAddress((void**)&kvx,  g_kvx);
    cudaGetSymbolAddress((void**)&att,  g_att);
    cudaGetSymbolAddress((void**)&h,    g_h);
    cudaGetSymbolAddress((void**)&ffn,  g_ffn);
    cudaGetSymbolAddress((void**)&wr,   g_wr);
    cudaGetSymbolAddress((void**)&encr, g_encr);

    cudaFuncSetAttribute(mma_gemm<false,false,true>, cudaFuncAttributeMaxDynamicSharedMemorySize, GEMM_SMEM);
    cudaFuncSetAttribute(mma_gemm<false,true,false>, cudaFuncAttributeMaxDynamicSharedMemorySize, GEMM_SMEM);
    cudaFuncSetAttribute(mma_gemm<true,false,true>,  cudaFuncAttributeMaxDynamicSharedMemorySize, GEMM_SMEM);
    cudaFuncSetAttribute(flash_kernel<true>,  cudaFuncAttributeMaxDynamicSharedMemorySize, FL_SMEM);
    cudaFuncSetAttribute(flash_kernel<false>, cudaFuncAttributeMaxDynamicSharedMemorySize, FL_SMEM);

    // ---- pre-round / concat weights + encoder ----
    int n4_dd = DMODEL * DMODEL / 4, n4_df = DMODEL * DFF / 4, n4_tok = TOK * DMODEL / 4;
    concat3_round<<<(1024 * 768 + 255) / 256, 256>>>(sa_q, sa_k, sa_v, wr + WR_QKV);
    round_copy<<<(n4_dd + 255) / 256, 256>>>(ca_q, wr + WR_CAQ, n4_dd);
    concat2_round<<<(1024 * 512 + 255) / 256, 256>>>(ca_k, ca_v, wr + WR_KVX);
    round_copy<<<(n4_dd + 255) / 256, 256>>>(sa_o, wr + WR_SAO, n4_dd);
    round_copy<<<(n4_dd + 255) / 256, 256>>>(ca_o, wr + WR_CAO, n4_dd);
    round_copy<<<(n4_df + 255) / 256, 256>>>(wi,   wr + WR_WI,  n4_df);
    round_copy<<<(n4_df + 255) / 256, 256>>>(wo,   wr + WR_WO,  n4_df);
    round_copy<<<(n4_tok + 255) / 256, 256>>>(enc, encr, n4_tok);

    dim3 gDD(DMODEL / 128, TOK / 128);      // (8, 32)
    dim3 gQKV(3072 / 128, TOK / 128);       // (24, 32)
    dim3 gKV(2048 / 128, TOK / 128);        // (16, 32)
    dim3 gDF(DFF / 128, TOK / 128);         // (32, 32)
    dim3 gFlash(LSEQ / 128, BATCH * HEADS); // (8, 64)

    bucket_kernel<<<1, 1024>>>();

    // ---- Self-attention ----
    rms_kernel<true><<<TOK, 256>>>(hid, ln1_w, xn);
    mma_gemm<false,false,true><<<gQKV, 128, GEMM_SMEM>>>(xn, wr + WR_QKV, nullptr, qkv, TOK, 3072, DMODEL);
    flash_kernel<true><<<gFlash, 256, FL_SMEM>>>(qkv, 3072, qkv + 1024, 3072, qkv + 2048, 3072,
                                                 relb, dmask, att);
    mma_gemm<false,true,false><<<gDD, 128, GEMM_SMEM>>>(att, wr + WR_SAO, hid, h, TOK, DMODEL, DMODEL);

    // ---- Cross-attention ----
    rms_kernel<true><<<TOK, 256>>>(h, ln2_w, xn);
    mma_gemm<false,false,true><<<gDD, 128, GEMM_SMEM>>>(xn,   wr + WR_CAQ, nullptr, qkv, TOK, DMODEL, DMODEL);
    mma_gemm<false,false,true><<<gKV, 128, GEMM_SMEM>>>(encr, wr + WR_KVX, nullptr, kvx, TOK, 2048, DMODEL);
    flash_kernel<false><<<gFlash, 256, FL_SMEM>>>(qkv, 1024, kvx, 2048, kvx + 1024, 2048,
                                                  nullptr, emask, att);
    mma_gemm<false,true,false><<<gDD, 128, GEMM_SMEM>>>(att, wr + WR_CAO, h, h, TOK, DMODEL, DMODEL);

    // ---- FFN ----
    rms_kernel<true><<<TOK, 256>>>(h, ln3_w, xn);
    mma_gemm<true,false,true><<<gDF, 128, GEMM_SMEM>>>(xn, wr + WR_WI, nullptr, ffn, TOK, DFF, DMODEL);
    mma_gemm<false,true,false><<<gDD, 128, GEMM_SMEM>>>(ffn, wr + WR_WO, h, h, TOK, DMODEL, DFF);

    // ---- Final norm ----
    rms_kernel<false><<<TOK, 256>>>(h, flnw, out);
}

// round 7
// speedup vs baseline: 6.7265x; 1.7239x over previous
#include <cuda_runtime.h>
#include <cuda_fp16.h>
#include <math.h>
#include <stdint.h>

// ---------------- Problem constants ----------------
#define BATCH 4
#define LSEQ  1024
#define DMODEL 1024
#define HEADS 16
#define DKV   64
#define DFF   4096
#define TOK   (BATCH * LSEQ)
#define NBUCK 32
#define NEGINF (-1e9f)

// ---------------- Scratch ----------------
__device__ __half g_xnorm[TOK * DMODEL];
__device__ __half g_qkv[TOK * 3072];
__device__ __half g_kvx[TOK * 2048];
__device__ __half g_att[TOK * DMODEL];
__device__ float  g_h[TOK * DMODEL];
__device__ __half g_encr[TOK * DMODEL];
__device__ __half g_ffn[TOK * DFF];
__device__ __half g_wh[16 * 1024 * 1024];   // fp16 weights, transposed [N][K]
__device__ int    g_bucket[LSEQ];

#define WH_QKV 0                        // [3072][1024]
#define WH_CAQ (3 * 1048576)            // [1024][1024]
#define WH_KVX (4 * 1048576)            // [2048][1024]
#define WH_SAO (6 * 1048576)
#define WH_CAO (7 * 1048576)
#define WH_WI  (8 * 1048576)            // [4096][1024]
#define WH_WO  (12 * 1048576)           // [1024][4096]

// ---------------- helpers ----------------
__device__ __forceinline__ void mma_f16(float (&d)[4], const uint32_t (&a)[4],
                                        uint32_t b0, uint32_t b1) {
    asm volatile(
        "mma.sync.aligned.m16n8k16.row.col.f32.f16.f16.f32 "
        "{%0,%1,%2,%3}, {%4,%5,%6,%7}, {%8,%9}, {%0,%1,%2,%3};"
        : "+f"(d[0]), "+f"(d[1]), "+f"(d[2]), "+f"(d[3])
        : "r"(a[0]), "r"(a[1]), "r"(a[2]), "r"(a[3]), "r"(b0), "r"(b1));
}
__device__ __forceinline__ void ldsm4(uint32_t (&r)[4], uint32_t addr) {
    asm volatile("ldmatrix.sync.aligned.m8n8.x4.shared.b16 {%0,%1,%2,%3}, [%4];"
                 : "=r"(r[0]), "=r"(r[1]), "=r"(r[2]), "=r"(r[3]) : "r"(addr));
}
__device__ __forceinline__ void ldsm4t(uint32_t (&r)[4], uint32_t addr) {
    asm volatile("ldmatrix.sync.aligned.m8n8.x4.trans.shared.b16 {%0,%1,%2,%3}, [%4];"
                 : "=r"(r[0]), "=r"(r[1]), "=r"(r[2]), "=r"(r[3]) : "r"(addr));
}
__device__ __forceinline__ void cp16s(uint32_t dst, const void* src) {
    asm volatile("cp.async.cg.shared.global [%0], [%1], 16;" :: "r"(dst), "l"(src));
}
__device__ __forceinline__ void cp_commit() { asm volatile("cp.async.commit_group;"); }
__device__ __forceinline__ void cp_wait0()  { asm volatile("cp.async.wait_group 0;" ::: "memory"); }

// ---------------- prep: transpose fp32 [K][N] -> fp16 [N][K] --------------
__global__ void transpose_h(const float* __restrict__ W, __half* __restrict__ Wt,
                            int K, int N) {
    __shared__ float t[32][33];
    int n0 = blockIdx.x * 32, k0 = blockIdx.y * 32;
    int x = threadIdx.x, y = threadIdx.y;
    #pragma unroll
    for (int i = 0; i < 32; i += 8)
        t[y + i][x] = W[(size_t)(k0 + y + i) * N + n0 + x];
    __syncthreads();
    #pragma unroll
    for (int i = 0; i < 32; i += 8)
        Wt[(size_t)(n0 + y + i) * K + k0 + x] = __float2half(t[x][y + i]);
}

__global__ void conv_half(const float* __restrict__ src, __half* __restrict__ dst, int n4) {
    int i = blockIdx.x * 256 + threadIdx.x;
    if (i < n4) {
        float4 v = ((const float4*)src)[i];
        __half2* d = (__half2*)(dst + (size_t)i * 4);
        d[0] = __floats2half2_rn(v.x, v.y);
        d[1] = __floats2half2_rn(v.z, v.w);
    }
}

// ---------------- RMS norm ----------------
template<bool HOUT>
__global__ void rms_kernel(const float* __restrict__ x,
                           const float* __restrict__ w, void* __restrict__ yv) {
    int row = blockIdx.x;
    const float* xr = x + (size_t)row * DMODEL;
    float s = 0.f;
    for (int i = threadIdx.x; i < DMODEL; i += 256) {
        float v = xr[i];
        s += v * v;
    }
    __shared__ float red[8];
    #pragma unroll
    for (int o = 16; o; o >>= 1) s += __shfl_xor_sync(0xffffffffu, s, o);
    if ((threadIdx.x & 31) == 0) red[threadIdx.x >> 5] = s;
    __syncthreads();
    if (threadIdx.x < 8) {
        float t = red[threadIdx.x];
        #pragma unroll
        for (int o = 4; o; o >>= 1) t += __shfl_xor_sync(0xffu, t, o);
        if (threadIdx.x == 0) red[0] = rsqrtf(t * (1.0f / DMODEL) + 1e-6f);
    }
    __syncthreads();
    float inv = red[0];
    for (int i = threadIdx.x; i < DMODEL; i += 256) {
        float v = xr[i] * inv * w[i];
        if (HOUT) ((__half*)yv)[(size_t)row * DMODEL + i] = __float2half(v);
        else      ((float*)yv)[(size_t)row * DMODEL + i] = v;
    }
}

// ---------------- fp16 GEMM: C[M,N] = A[M,K] @ Bt[N,K]^T (+R)(ReLU) -------
// Block 128x128x64, 256 thr = 8 warps (2M x 4N), warp 64x32. ldmatrix frags.
// smem rows: 128B data + 16B skew = 144B stride (conflict-free ldmatrix).
#define GSM_TILE 18432
#define GEMM_SMEM (4 * GSM_TILE)

template<bool RELU, bool RES, bool HOUT>
__global__ void __launch_bounds__(256, 2)
hgemm(const __half* __restrict__ A, const __half* __restrict__ B,
      const float* __restrict__ R, void* __restrict__ Cv,
      int M, int N, int K) {
    extern __shared__ char smc[];
    uint32_t S = (uint32_t)__cvta_generic_to_shared(smc);
    const int tid = threadIdx.x;
    const int warp = tid >> 5, lane = tid & 31;
    const int gid = lane >> 2, tg = lane & 3;
    const int wm = warp & 1, wn = warp >> 1;
    const int m0 = blockIdx.y * 128, n0 = blockIdx.x * 128;
    const __half* Ag = A + (size_t)m0 * K;
    const __half* Bg = B + (size_t)n0 * K;

    float acc[4][4][4];
    #pragma unroll
    for (int i = 0; i < 4; i++)
        #pragma unroll
        for (int j = 0; j < 4; j++)
            #pragma unroll
            for (int l = 0; l < 4; l++) acc[i][j][l] = 0.f;

    #define GLOAD(kt, s) do {                                                 \
        uint32_t ab = S + (s) * GSM_TILE;                                     \
        uint32_t bb = S + 2 * GSM_TILE + (s) * GSM_TILE;                      \
        _Pragma("unroll")                                                     \
        for (int i = 0; i < 4; i++) {                                         \
            int idx = tid + i * 256;                                          \
            int r = idx >> 3, c = idx & 7;                                    \
            cp16s(ab + r * 144 + c * 16, Ag + (size_t)r * K + (kt) + c * 8);  \
            cp16s(bb + r * 144 + c * 16, Bg + (size_t)r * K + (kt) + c * 8);  \
        }                                                                     \
        cp_commit();                                                          \
    } while (0)

    GLOAD(0, 0);
    cp_wait0();
    __syncthreads();

    int s = 0;
    for (int kt = 0; kt < K; kt += 64) {
        bool more = (kt + 64 < K);
        if (more) GLOAD(kt + 64, s ^ 1);
        uint32_t ab = S + s * GSM_TILE;
        uint32_t bb = S + 2 * GSM_TILE + s * GSM_TILE;
        #pragma unroll
        for (int ks = 0; ks < 4; ks++) {
            uint32_t af[4][4], bf[2][4];
            #pragma unroll
            for (int mt = 0; mt < 4; mt++)
                ldsm4(af[mt], ab + (wm * 64 + mt * 16 + (lane & 15)) * 144
                              + ks * 32 + (lane >> 4) * 16);
            #pragma unroll
            for (int g = 0; g < 2; g++)
                ldsm4(bf[g], bb + (wn * 32 + g * 16 + ((lane >> 4) << 3) + (lane & 7)) * 144
                             + ks * 32 + ((lane >> 3) & 1) * 16);
            #pragma unroll
            for (int mt = 0; mt < 4; mt++)
                #pragma unroll
                for (int nt = 0; nt < 4; nt++)
                    mma_f16(acc[mt][nt], af[mt],
                            bf[nt >> 1][(nt & 1) * 2], bf[nt >> 1][(nt & 1) * 2 + 1]);
        }
        if (more) cp_wait0();
        __syncthreads();
        s ^= 1;
    }

    #pragma unroll
    for (int mt = 0; mt < 4; mt++) {
        #pragma unroll
        for (int nt = 0; nt < 4; nt++) {
            int r0 = m0 + wm * 64 + mt * 16 + gid;
            int c  = n0 + wn * 32 + nt * 8 + tg * 2;
            float2 v0 = make_float2(acc[mt][nt][0], acc[mt][nt][1]);
            float2 v1 = make_float2(acc[mt][nt][2], acc[mt][nt][3]);
            if (RES) {
                float2 a0 = *(const float2*)(R + (size_t)r0 * N + c);
                float2 a1 = *(const float2*)(R + (size_t)(r0 + 8) * N + c);
                v0.x += a0.x; v0.y += a0.y; v1.x += a1.x; v1.y += a1.y;
            }
            if (RELU) {
                v0.x = fmaxf(v0.x, 0.f); v0.y = fmaxf(v0.y, 0.f);
                v1.x = fmaxf(v1.x, 0.f); v1.y = fmaxf(v1.y, 0.f);
            }
            if (HOUT) {
                __half* C = (__half*)Cv;
                *(__half2*)(C + (size_t)r0 * N + c)       = __floats2half2_rn(v0.x, v0.y);
                *(__half2*)(C + (size_t)(r0 + 8) * N + c) = __floats2half2_rn(v1.x, v1.y);
            } else {
                float* C = (float*)Cv;
                *(float2*)(C + (size_t)r0 * N + c) = v0;
                *(float2*)(C + (size_t)(r0 + 8) * N + c) = v1;
            }
        }
    }
    #undef GLOAD
}

// ---------------- T5 relative bucket table ----------------
__global__ void bucket_kernel() {
    int n = threadIdx.x;
    int b;
    if (n < 16) {
        b = n;
    } else {
        float nf = (float)n;
        int vl = 16 + (int)(logf(nf / 16.0f) / logf(8.0f) * 16.0f);
        b = vl < (NBUCK - 1) ? vl : (NBUCK - 1);
    }
    g_bucket[n] = b;
}

// ---------------- Fused fp16 flash attention ----------------
// Per CTA: one (b,h), one 128-row q tile. 256 threads = 8 warps.
// QK: warps 2M x 4N (64x32). PV: warps 4M x 2N (32x32). ldmatrix everywhere.
#define FQ_OFF 0
#define FK_OFF 18432
#define FV_OFF 36864
#define FP_OFF 55296
#define FMP_OFF 90112
#define FLP_OFF 92160
#define FMR_OFF 94208
#define FLR_OFF 95232
#define FL_SMEM 95744

template<bool SELF>
__global__ void __launch_bounds__(256)
flash_h(const __half* __restrict__ Qp, int qstride,
        const __half* __restrict__ Kp, int kstride,
        const __half* __restrict__ Vp, int vstride,
        const float* __restrict__ relb, const int* __restrict__ mask,
        __half* __restrict__ O) {
    extern __shared__ char smc[];
    uint32_t S = (uint32_t)__cvta_generic_to_shared(smc);
    float* mpart = (float*)(smc + FMP_OFF);
    float* lpart = (float*)(smc + FLP_OFF);
    float* mrun  = (float*)(smc + FMR_OFF);
    float* lrun  = (float*)(smc + FLR_OFF);

    int tid = threadIdx.x;
    int warp = tid >> 5, lane = tid & 31;
    int gid = lane >> 2, tg = lane & 3;
    int wm = warp & 1, wn = warp >> 1;
    int pm = warp & 3, pn = warp >> 2;
    int qt = blockIdx.x;
    int q0 = qt * 128;
    int bh = blockIdx.y;
    int b = bh >> 4, h = bh & 15;

    const __half* Qg = Qp + (size_t)(b * LSEQ + q0) * qstride + h * DKV;
    const __half* Kg = Kp + (size_t)(b * LSEQ) * kstride + h * DKV;
    const __half* Vg = Vp + (size_t)(b * LSEQ) * vstride + h * DKV;

    if (tid < 128) { mrun[tid] = -1e30f; lrun[tid] = 0.f; }

    #pragma unroll
    for (int i = 0; i < 4; i++) {
        int idx = tid + i * 256;
        int r = idx >> 3, c = idx & 7;
        cp16s(S + FQ_OFF + r * 144 + c * 16, Qg + (size_t)r * qstride + c * 8);
    }
    cp_commit();

    float oacc[2][4][4];
    #pragma unroll
    for (int i = 0; i < 2; i++)
        #pragma unroll
        for (int j = 0; j < 4; j++)
            #pragma unroll
            for (int l = 0; l < 4; l++) oacc[i][j][l] = 0.f;

    const int niter = SELF ? (qt + 1) : (LSEQ / 128);
    int p = 0;

    for (int it = 0; it < niter; it++) {
        int k0 = it * 128;
        #pragma unroll
        for (int i = 0; i < 4; i++) {
            int idx = tid + i * 256;
            int r = idx >> 3, c = idx & 7;
            cp16s(S + FK_OFF + r * 144 + c * 16, Kg + (size_t)(k0 + r) * kstride + c * 8);
            cp16s(S + FV_OFF + r * 144 + c * 16, Vg + (size_t)(k0 + r) * vstride + c * 8);
        }
        cp_commit();
        cp_wait0();
        __syncthreads();

        // ---- QK^T ----
        float sacc[4][4][4];
        #pragma unroll
        for (int i = 0; i < 4; i++)
            #pragma unroll
            for (int j = 0; j < 4; j++)
                #pragma unroll
                for (int l = 0; l < 4; l++) sacc[i][j][l] = 0.f;

        #pragma unroll
        for (int ks = 0; ks < 4; ks++) {
            uint32_t af[4][4], bf[2][4];
            #pragma unroll
            for (int mt = 0; mt < 4; mt++)
                ldsm4(af[mt], S + FQ_OFF + (wm * 64 + mt * 16 + (lane & 15)) * 144
                              + ks * 32 + (lane >> 4) * 16);
            #pragma unroll
            for (int g = 0; g < 2; g++)
                ldsm4(bf[g], S + FK_OFF + (wn * 32 + g * 16 + ((lane >> 4) << 3) + (lane & 7)) * 144
                             + ks * 32 + ((lane >> 3) & 1) * 16);
            #pragma unroll
            for (int mt = 0; mt < 4; mt++)
                #pragma unroll
                for (int nt = 0; nt < 4; nt++)
                    mma_f16(sacc[mt][nt], af[mt],
                            bf[nt >> 1][(nt & 1) * 2], bf[nt >> 1][(nt & 1) * 2 + 1]);
        }

        // ---- bias + mask ----
        bool cok[4][2];
        int ccol[4];
        #pragma unroll
        for (int nf = 0; nf < 4; nf++) {
            int c = k0 + wn * 32 + nf * 8 + tg * 2;
            ccol[nf] = c;
            cok[nf][0] = mask[b * LSEQ + c] > 0;
            cok[nf][1] = mask[b * LSEQ + c + 1] > 0;
        }
        #pragma unroll
        for (int mf = 0; mf < 4; mf++) {
            #pragma unroll
            for (int half = 0; half < 2; half++) {
                int qi = q0 + wm * 64 + mf * 16 + gid + half * 8;
                #pragma unroll
                for (int nf = 0; nf < 4; nf++) {
                    int c = ccol[nf];
                    if (SELF) {
                        int d0 = qi - c, d1 = d0 - 1;
                        sacc[mf][nf][half * 2]     += relb[g_bucket[d0 > 0 ? d0 : 0] * HEADS + h];
                        sacc[mf][nf][half * 2 + 1] += relb[g_bucket[d1 > 0 ? d1 : 0] * HEADS + h];
                        if (!((c     <= qi) && cok[nf][0])) sacc[mf][nf][half * 2]     += NEGINF;
                        if (!((c + 1 <= qi) && cok[nf][1])) sacc[mf][nf][half * 2 + 1] += NEGINF;
                    } else {
                        if (!cok[nf][0]) sacc[mf][nf][half * 2]     += NEGINF;
                        if (!cok[nf][1]) sacc[mf][nf][half * 2 + 1] += NEGINF;
                    }
                }
            }
        }

        // ---- partial row max ----
        #pragma unroll
        for (int mf = 0; mf < 4; mf++) {
            float mx0 = -1e30f, mx1 = -1e30f;
            #pragma unroll
            for (int nf = 0; nf < 4; nf++) {
                mx0 = fmaxf(mx0, fmaxf(sacc[mf][nf][0], sacc[mf][nf][1]));
                mx1 = fmaxf(mx1, fmaxf(sacc[mf][nf][2], sacc[mf][nf][3]));
            }
            mx0 = fmaxf(mx0, __shfl_xor_sync(0xffffffffu, mx0, 1));
            mx0 = fmaxf(mx0, __shfl_xor_sync(0xffffffffu, mx0, 2));
            mx1 = fmaxf(mx1, __shfl_xor_sync(0xffffffffu, mx1, 1));
            mx1 = fmaxf(mx1, __shfl_xor_sync(0xffffffffu, mx1, 2));
            if (tg == 0) {
                int r0 = wm * 64 + mf * 16 + gid;
                mpart[r0 * 4 + wn] = mx0;
                mpart[(r0 + 8) * 4 + wn] = mx1;
            }
        }
        __syncthreads();

        // ---- m_new, exp, P store (half), partial sums ----
        float* mold  = mrun + p * 128;
        float* mnewa = mrun + (p ^ 1) * 128;
        #pragma unroll
        for (int mf = 0; mf < 4; mf++) {
            #pragma unroll
            for (int half = 0; half < 2; half++) {
                int r = wm * 64 + mf * 16 + gid + half * 8;
                float mt = fmaxf(fmaxf(mpart[r * 4 + 0], mpart[r * 4 + 1]),
                                 fmaxf(mpart[r * 4 + 2], mpart[r * 4 + 3]));
                float mn = fmaxf(mold[r], mt);
                if (wn == 0 && tg == 0) mnewa[r] = mn;
                float sum = 0.f;
                #pragma unroll
                for (int nf = 0; nf < 4; nf++) {
                    float e0 = __expf(sacc[mf][nf][half * 2]     - mn);
                    float e1 = __expf(sacc[mf][nf][half * 2 + 1] - mn);
                    sum += e0 + e1;
                    int col = wn * 32 + nf * 8 + tg * 2;
                    *(__half2*)(smc + FP_OFF + r * 272 + col * 2) = __floats2half2_rn(e0, e1);
                }
                sum += __shfl_xor_sync(0xffffffffu, sum, 1);
                sum += __shfl_xor_sync(0xffffffffu, sum, 2);
                if (tg == 0) lpart[r * 4 + wn] = sum;
            }
        }
        __syncthreads();

        // ---- rescale O, update running sum ----
        #pragma unroll
        for (int mt2 = 0; mt2 < 2; mt2++) {
            #pragma unroll
            for (int half = 0; half < 2; half++) {
                int r = pm * 32 + mt2 * 16 + gid + half * 8;
                float rs = __expf(mold[r] - mnewa[r]);
                #pragma unroll
                for (int nf = 0; nf < 4; nf++) {
                    oacc[mt2][nf][half * 2]     *= rs;
                    oacc[mt2][nf][half * 2 + 1] *= rs;
                }
                if (pn == 0 && tg == 0)
                    lrun[r] = lrun[r] * rs + lpart[r * 4 + 0] + lpart[r * 4 + 1]
                                           + lpart[r * 4 + 2] + lpart[r * 4 + 3];
            }
        }

        // ---- P @ V ----
        #pragma unroll
        for (int ks = 0; ks < 8; ks++) {
            uint32_t af[2][4], bf[2][4];
            #pragma unroll
            for (int mt2 = 0; mt2 < 2; mt2++)
                ldsm4(af[mt2], S + FP_OFF + (pm * 32 + mt2 * 16 + (lane & 15)) * 272
                               + ks * 32 + (lane >> 4) * 16);
            #pragma unroll
            for (int g = 0; g < 2; g++)
                ldsm4t(bf[g], S + FV_OFF + (ks * 16 + ((lane >> 3) & 1) * 8 + (lane & 7)) * 144
                              + pn * 64 + g * 32 + (lane >> 4) * 16);
            #pragma unroll
            for (int mt2 = 0; mt2 < 2; mt2++)
                #pragma unroll
                for (int nt = 0; nt < 4; nt++)
                    mma_f16(oacc[mt2][nt], af[mt2],
                            bf[nt >> 1][(nt & 1) * 2], bf[nt >> 1][(nt & 1) * 2 + 1]);
        }

        __syncthreads();
        p ^= 1;
    }

    // ---- normalize, store half ----
    #pragma unroll
    for (int mt2 = 0; mt2 < 2; mt2++) {
        int rloc0 = pm * 32 + mt2 * 16 + gid;
        float inv0 = 1.0f / lrun[rloc0];
        float inv1 = 1.0f / lrun[rloc0 + 8];
        #pragma unroll
        for (int nf = 0; nf < 4; nf++) {
            int col = h * DKV + pn * 32 + nf * 8 + tg * 2;
            size_t row0 = (size_t)(b * LSEQ + q0 + rloc0);
            *(__half2*)(O + row0 * DMODEL + col)
                = __floats2half2_rn(oacc[mt2][nf][0] * inv0, oacc[mt2][nf][1] * inv0);
            *(__half2*)(O + (row0 + 8) * DMODEL + col)
                = __floats2half2_rn(oacc[mt2][nf][2] * inv1, oacc[mt2][nf][3] * inv1);
        }
    }
}

// ---------------- Orchestration -------------------------------------------
extern "C" void kernel_launch(void* const* d_in, const int* in_sizes, int n_in,
                              void* d_out, int out_size) {
    const float* enc    = (const float*)d_in[0];
    const float* hid    = (const float*)d_in[1];
    const float* ln1_w  = (const float*)d_in[2];
    const float* sa_q   = (const float*)d_in[3];
    const float* sa_k   = (const float*)d_in[4];
    const float* sa_v   = (const float*)d_in[5];
    const float* sa_o   = (const float*)d_in[6];
    const float* relb   = (const float*)d_in[7];
    const float* ln2_w  = (const float*)d_in[8];
    const float* ca_q   = (const float*)d_in[9];
    const float* ca_k   = (const float*)d_in[10];
    const float* ca_v   = (const float*)d_in[11];
    const float* ca_o   = (const float*)d_in[12];
    const float* ln3_w  = (const float*)d_in[13];
    const float* wi     = (const float*)d_in[14];
    const float* wo     = (const float*)d_in[15];
    const float* flnw   = (const float*)d_in[16];
    const int*   emask  = (const int*)d_in[17];
    const int*   dmask  = (const int*)d_in[18];
    float* out = (float*)d_out;

    __half *xn, *qkv, *kvx, *att, *encr, *ffn, *wh;
    float *h;
    cudaGetSymbolAddress((void**)&xn,   g_xnorm);
    cudaGetSymbolAddress((void**)&qkv,  g_qkv);
    cudaGetSymbolAddress((void**)&kvx,  g_kvx);
    cudaGetSymbolAddress((void**)&att,  g_att);
    cudaGetSymbolAddress((void**)&h,    g_h);
    cudaGetSymbolAddress((void**)&encr, g_encr);
    cudaGetSymbolAddress((void**)&ffn,  g_ffn);
    cudaGetSymbolAddress((void**)&wh,   g_wh);

    cudaFuncSetAttribute(hgemm<false,false,true>, cudaFuncAttributeMaxDynamicSharedMemorySize, GEMM_SMEM);
    cudaFuncSetAttribute(hgemm<false,true,false>, cudaFuncAttributeMaxDynamicSharedMemorySize, GEMM_SMEM);
    cudaFuncSetAttribute(hgemm<true,false,true>,  cudaFuncAttributeMaxDynamicSharedMemorySize, GEMM_SMEM);
    cudaFuncSetAttribute(flash_h<true>,  cudaFuncAttributeMaxDynamicSharedMemorySize, FL_SMEM);
    cudaFuncSetAttribute(flash_h<false>, cudaFuncAttributeMaxDynamicSharedMemorySize, FL_SMEM);

    // ---- prep: weights -> fp16 transposed [N][K]; encoder -> fp16 ----
    dim3 tb(32, 8);
    dim3 tDD(32, 32);
    transpose_h<<<tDD, tb>>>(sa_q, wh + WH_QKV,               DMODEL, DMODEL);
    transpose_h<<<tDD, tb>>>(sa_k, wh + WH_QKV + 1048576,     DMODEL, DMODEL);
    transpose_h<<<tDD, tb>>>(sa_v, wh + WH_QKV + 2 * 1048576, DMODEL, DMODEL);
    transpose_h<<<tDD, tb>>>(ca_q, wh + WH_CAQ,               DMODEL, DMODEL);
    transpose_h<<<tDD, tb>>>(ca_k, wh + WH_KVX,               DMODEL, DMODEL);
    transpose_h<<<tDD, tb>>>(ca_v, wh + WH_KVX + 1048576,     DMODEL, DMODEL);
    transpose_h<<<tDD, tb>>>(sa_o, wh + WH_SAO,               DMODEL, DMODEL);
    transpose_h<<<tDD, tb>>>(ca_o, wh + WH_CAO,               DMODEL, DMODEL);
    transpose_h<<<dim3(128, 32), tb>>>(wi, wh + WH_WI, DMODEL, DFF);
    transpose_h<<<dim3(32, 128), tb>>>(wo, wh + WH_WO, DFF, DMODEL);
    conv_half<<<(TOK * DMODEL / 4 + 255) / 256, 256>>>(enc, encr, TOK * DMODEL / 4);

    dim3 gDD(8, 32);
    dim3 gQKV(24, 32);
    dim3 gKV(16, 32);
    dim3 gDF(32, 32);
    dim3 gFlash(LSEQ / 128, BATCH * HEADS);

    bucket_kernel<<<1, 1024>>>();

    // ---- Self-attention ----
    rms_kernel<true><<<TOK, 256>>>(hid, ln1_w, xn);
    hgemm<false,false,true><<<gQKV, 256, GEMM_SMEM>>>(xn, wh + WH_QKV, nullptr, qkv, TOK, 3072, DMODEL);
    flash_h<true><<<gFlash, 256, FL_SMEM>>>(qkv, 3072, qkv + 1024, 3072, qkv + 2048, 3072,
                                            relb, dmask, att);
    hgemm<false,true,false><<<gDD, 256, GEMM_SMEM>>>(att, wh + WH_SAO, hid, h, TOK, DMODEL, DMODEL);

    // ---- Cross-attention ----
    rms_kernel<true><<<TOK, 256>>>(h, ln2_w, xn);
    hgemm<false,false,true><<<gDD, 256, GEMM_SMEM>>>(xn, wh + WH_CAQ, nullptr, qkv, TOK, DMODEL, DMODEL);
    hgemm<false,false,true><<<gKV, 256, GEMM_SMEM>>>(encr, wh + WH_KVX, nullptr, kvx, TOK, 2048, DMODEL);
    flash_h<false><<<gFlash, 256, FL_SMEM>>>(qkv, 1024, kvx, 2048, kvx + 1024, 2048,
                                             nullptr, emask, att);
    hgemm<false,true,false><<<gDD, 256, GEMM_SMEM>>>(att, wh + WH_CAO, h, h, TOK, DMODEL, DMODEL);

    // ---- FFN ----
    rms_kernel<true><<<TOK, 256>>>(h, ln3_w, xn);
    hgemm<true,false,true><<<gDF, 256, GEMM_SMEM>>>(xn, wh + WH_WI, nullptr, ffn, TOK, DFF, DMODEL);
    hgemm<false,true,false><<<gDD, 256, GEMM_SMEM>>>(ffn, wh + WH_WO, h, h, TOK, DMODEL, DFF);

    // ---- Final norm ----
    rms_kernel<false><<<TOK, 256>>>(h, flnw, out);
}